// round 2
// baseline (speedup 1.0000x reference)
#include <cuda_runtime.h>
#include <cuda_bf16.h>

// Problem constants
#define Nn  8192
#define FIN 512
#define HH  256
#define LL  64
#define EE  262144

// Scratch (device globals; no allocation allowed)
__device__ float g_deg[Nn];
__device__ float g_dinv[Nn];
__device__ float g_xw1[Nn * HH];     // x @ W1
__device__ float g_h[Nn * HH];       // acc then relu'd hidden
__device__ float g_uv[Nn * 128];     // [h@Wmu | h@Wsig]
__device__ float g_uvagg[Nn * 128];  // aggregated heads
__device__ float g_z[Nn * LL];       // latent z

__device__ __forceinline__ float sigf(float x) {
    return 1.0f / (1.0f + __expf(-x));
}

// ---------------- degree / dinv ----------------
__global__ void k_zero_deg() {
    int i = blockIdx.x * blockDim.x + threadIdx.x;
    if (i < Nn) g_deg[i] = 0.f;
}

__global__ void k_deg(const int* __restrict__ ei) {
    int e = blockIdx.x * blockDim.x + threadIdx.x;
    if (e < EE) atomicAdd(&g_deg[ei[EE + e]], 1.0f);
}

__global__ void k_dinv() {
    int i = blockIdx.x * blockDim.x + threadIdx.x;
    if (i < Nn) g_dinv[i] = rsqrtf(g_deg[i] + 1.0f);
}

// ---------------- GEMM1: g_xw1 = x @ W1  (8192x512x256) ----------------
__global__ __launch_bounds__(256, 2) void k_gemm1(const float* __restrict__ A,
                                                  const float* __restrict__ B) {
    __shared__ float As[32][128];
    __shared__ float Bs[32][128];
    int tid = threadIdx.x;
    int n0 = blockIdx.x * 128, m0 = blockIdx.y * 128;
    int tx = tid & 15, ty = tid >> 4;
    float acc[8][8] = {};

    for (int kt = 0; kt < FIN; kt += 32) {
#pragma unroll
        for (int i = 0; i < 4; i++) {
            int v = i * 256 + tid;
            int m = v & 127, kq = v >> 7;
            float4 f = *(const float4*)(A + (size_t)(m0 + m) * FIN + kt + kq * 4);
            As[kq * 4 + 0][m] = f.x; As[kq * 4 + 1][m] = f.y;
            As[kq * 4 + 2][m] = f.z; As[kq * 4 + 3][m] = f.w;
        }
#pragma unroll
        for (int i = 0; i < 4; i++) {
            int v = i * 256 + tid;
            int kk = v >> 5, n4 = (v & 31) * 4;
            *(float4*)&Bs[kk][n4] =
                *(const float4*)(B + (size_t)(kt + kk) * HH + n0 + n4);
        }
        __syncthreads();
#pragma unroll
        for (int kk = 0; kk < 32; kk++) {
            float a[8], b[8];
            *(float4*)(a)     = *(float4*)&As[kk][ty * 8];
            *(float4*)(a + 4) = *(float4*)&As[kk][ty * 8 + 4];
            *(float4*)(b)     = *(float4*)&Bs[kk][tx * 8];
            *(float4*)(b + 4) = *(float4*)&Bs[kk][tx * 8 + 4];
#pragma unroll
            for (int r = 0; r < 8; r++)
#pragma unroll
                for (int c = 0; c < 8; c++) acc[r][c] += a[r] * b[c];
        }
        __syncthreads();
    }
#pragma unroll
    for (int r = 0; r < 8; r++) {
        int gm = m0 + ty * 8 + r;
        *(float4*)(g_xw1 + (size_t)gm * HH + n0 + tx * 8)     = *(float4*)&acc[r][0];
        *(float4*)(g_xw1 + (size_t)gm * HH + n0 + tx * 8 + 4) = *(float4*)&acc[r][4];
    }
}

// ---------------- aggregation layer 1 ----------------
__global__ void k_init_acc1() {
    int t4 = blockIdx.x * blockDim.x + threadIdx.x;  // float4 index
    if (t4 < Nn * HH / 4) {
        int node = t4 >> 6;  // 64 float4 per row
        float d = g_dinv[node];
        float d2 = d * d;
        float4 v = *((const float4*)g_xw1 + t4);
        v.x *= d2; v.y *= d2; v.z *= d2; v.w *= d2;
        *((float4*)g_h + t4) = v;
    }
}

__global__ void k_scatter_h(const int* __restrict__ ei) {
    int gt = blockIdx.x * blockDim.x + threadIdx.x;
    int w = gt >> 5, lane = gt & 31;
    if (w >= EE) return;
    int src = ei[w], dst = ei[EE + w];
    float norm = g_dinv[src] * g_dinv[dst];
    const float4* s4 = (const float4*)(g_xw1 + (size_t)src * HH);
    float* d = g_h + (size_t)dst * HH;
#pragma unroll
    for (int j = 0; j < 2; j++) {
        int idx = lane + j * 32;
        float4 v = s4[idx];
        atomicAdd(d + idx * 4 + 0, v.x * norm);
        atomicAdd(d + idx * 4 + 1, v.y * norm);
        atomicAdd(d + idx * 4 + 2, v.z * norm);
        atomicAdd(d + idx * 4 + 3, v.w * norm);
    }
}

__global__ void k_finalize_h(const float* __restrict__ b1) {
    int t = blockIdx.x * blockDim.x + threadIdx.x;
    if (t < Nn * HH) {
        float v = g_h[t] + b1[t & 255];
        g_h[t] = v > 0.f ? v : 0.f;
    }
}

// ------------- heads GEMM: g_uv = h @ [Wmu|Wsig]  (8192x256x128) -------------
__global__ __launch_bounds__(256, 2) void k_heads(const float* __restrict__ Wmu,
                                                  const float* __restrict__ Wsig) {
    __shared__ float As[32][128];
    __shared__ float Bs[32][128];
    int tid = threadIdx.x;
    int m0 = blockIdx.y * 128;
    int tx = tid & 15, ty = tid >> 4;
    float acc[8][8] = {};

    for (int kt = 0; kt < HH; kt += 32) {
#pragma unroll
        for (int i = 0; i < 4; i++) {
            int v = i * 256 + tid;
            int m = v & 127, kq = v >> 7;
            float4 f = *(const float4*)(g_h + (size_t)(m0 + m) * HH + kt + kq * 4);
            As[kq * 4 + 0][m] = f.x; As[kq * 4 + 1][m] = f.y;
            As[kq * 4 + 2][m] = f.z; As[kq * 4 + 3][m] = f.w;
        }
#pragma unroll
        for (int i = 0; i < 4; i++) {
            int v = i * 256 + tid;
            int kk = v >> 5, n4 = (v & 31) * 4;
            const float* Bp = (n4 < 64)
                ? (Wmu + (size_t)(kt + kk) * 64 + n4)
                : (Wsig + (size_t)(kt + kk) * 64 + (n4 - 64));
            *(float4*)&Bs[kk][n4] = *(const float4*)Bp;
        }
        __syncthreads();
#pragma unroll
        for (int kk = 0; kk < 32; kk++) {
            float a[8], b[8];
            *(float4*)(a)     = *(float4*)&As[kk][ty * 8];
            *(float4*)(a + 4) = *(float4*)&As[kk][ty * 8 + 4];
            *(float4*)(b)     = *(float4*)&Bs[kk][tx * 8];
            *(float4*)(b + 4) = *(float4*)&Bs[kk][tx * 8 + 4];
#pragma unroll
            for (int r = 0; r < 8; r++)
#pragma unroll
                for (int c = 0; c < 8; c++) acc[r][c] += a[r] * b[c];
        }
        __syncthreads();
    }
#pragma unroll
    for (int r = 0; r < 8; r++) {
        int gm = m0 + ty * 8 + r;
        *(float4*)(g_uv + (size_t)gm * 128 + tx * 8)     = *(float4*)&acc[r][0];
        *(float4*)(g_uv + (size_t)gm * 128 + tx * 8 + 4) = *(float4*)&acc[r][4];
    }
}

// ---------------- aggregation layer 2 (both heads at once) ----------------
__global__ void k_init_acc2() {
    int t4 = blockIdx.x * blockDim.x + threadIdx.x;  // float4 index over Nn*128
    if (t4 < Nn * 128 / 4) {
        int node = t4 >> 5;  // 32 float4 per row
        float d = g_dinv[node];
        float d2 = d * d;
        float4 v = *((const float4*)g_uv + t4);
        v.x *= d2; v.y *= d2; v.z *= d2; v.w *= d2;
        *((float4*)g_uvagg + t4) = v;
    }
}

__global__ void k_scatter_uv(const int* __restrict__ ei) {
    int gt = blockIdx.x * blockDim.x + threadIdx.x;
    int w = gt >> 5, lane = gt & 31;
    if (w >= EE) return;
    int src = ei[w], dst = ei[EE + w];
    float norm = g_dinv[src] * g_dinv[dst];
    const float4* s4 = (const float4*)(g_uv + (size_t)src * 128);
    float* d = g_uvagg + (size_t)dst * 128;
    float4 v = s4[lane];
    atomicAdd(d + lane * 4 + 0, v.x * norm);
    atomicAdd(d + lane * 4 + 1, v.y * norm);
    atomicAdd(d + lane * 4 + 2, v.z * norm);
    atomicAdd(d + lane * 4 + 3, v.w * norm);
}

// ---------------- z = gnoise * exp(xu) + xs ----------------
__global__ void k_z(const float* __restrict__ gn, const float* __restrict__ bmu,
                    const float* __restrict__ bsig) {
    int t = blockIdx.x * blockDim.x + threadIdx.x;
    if (t < Nn * LL) {
        int node = t >> 6, l = t & 63;
        float u = g_uvagg[(size_t)node * 128 + l] + bmu[l];
        float s = g_uvagg[(size_t)node * 128 + 64 + l] + bsig[l];
        g_z[t] = gn[t] * expf(u) + s;
    }
}

// ---------------- out = sigmoid(z @ z^T)  (8192x8192x64) ----------------
__global__ __launch_bounds__(256, 2) void k_zzt(float* __restrict__ out) {
    __shared__ float As[32][128];
    __shared__ float Bs[32][128];
    int tid = threadIdx.x;
    int n0 = blockIdx.x * 128, m0 = blockIdx.y * 128;
    int tx = tid & 15, ty = tid >> 4;
    float acc[8][8] = {};

    for (int kt = 0; kt < LL; kt += 32) {
#pragma unroll
        for (int i = 0; i < 4; i++) {
            int v = i * 256 + tid;
            int m = v & 127, kq = v >> 7;
            float4 fa = *(const float4*)(g_z + (size_t)(m0 + m) * LL + kt + kq * 4);
            As[kq * 4 + 0][m] = fa.x; As[kq * 4 + 1][m] = fa.y;
            As[kq * 4 + 2][m] = fa.z; As[kq * 4 + 3][m] = fa.w;
            float4 fb = *(const float4*)(g_z + (size_t)(n0 + m) * LL + kt + kq * 4);
            Bs[kq * 4 + 0][m] = fb.x; Bs[kq * 4 + 1][m] = fb.y;
            Bs[kq * 4 + 2][m] = fb.z; Bs[kq * 4 + 3][m] = fb.w;
        }
        __syncthreads();
#pragma unroll
        for (int kk = 0; kk < 32; kk++) {
            float a[8], b[8];
            *(float4*)(a)     = *(float4*)&As[kk][ty * 8];
            *(float4*)(a + 4) = *(float4*)&As[kk][ty * 8 + 4];
            *(float4*)(b)     = *(float4*)&Bs[kk][tx * 8];
            *(float4*)(b + 4) = *(float4*)&Bs[kk][tx * 8 + 4];
#pragma unroll
            for (int r = 0; r < 8; r++)
#pragma unroll
                for (int c = 0; c < 8; c++) acc[r][c] += a[r] * b[c];
        }
        __syncthreads();
    }
#pragma unroll
    for (int r = 0; r < 8; r++) {
        int gm = m0 + ty * 8 + r;
        float4 o0, o1;
        o0.x = sigf(acc[r][0]); o0.y = sigf(acc[r][1]);
        o0.z = sigf(acc[r][2]); o0.w = sigf(acc[r][3]);
        o1.x = sigf(acc[r][4]); o1.y = sigf(acc[r][5]);
        o1.z = sigf(acc[r][6]); o1.w = sigf(acc[r][7]);
        *(float4*)(out + (size_t)gm * Nn + n0 + tx * 8)     = o0;
        *(float4*)(out + (size_t)gm * Nn + n0 + tx * 8 + 4) = o1;
    }
}

// ---------------- launch ----------------
extern "C" void kernel_launch(void* const* d_in, const int* in_sizes, int n_in,
                              void* d_out, int out_size) {
    const float* x    = (const float*)d_in[0];
    const int*   ei   = (const int*)d_in[1];
    const float* W1   = (const float*)d_in[2];
    const float* b1   = (const float*)d_in[3];
    const float* Wmu  = (const float*)d_in[4];
    const float* bmu  = (const float*)d_in[5];
    const float* Wsig = (const float*)d_in[6];
    const float* bsig = (const float*)d_in[7];
    const float* gn   = (const float*)d_in[8];
    float* out = (float*)d_out;
    (void)in_sizes; (void)n_in; (void)out_size;

    k_zero_deg<<<Nn / 256, 256>>>();
    k_deg<<<EE / 256, 256>>>(ei);
    k_dinv<<<Nn / 256, 256>>>();

    k_gemm1<<<dim3(HH / 128, Nn / 128), 256>>>(x, W1);
    k_init_acc1<<<(Nn * HH / 4) / 256, 256>>>();
    k_scatter_h<<<(EE * 32) / 256, 256>>>(ei);
    k_finalize_h<<<(Nn * HH) / 256, 256>>>(b1);

    k_heads<<<dim3(1, Nn / 128), 256>>>(Wmu, Wsig);
    k_init_acc2<<<(Nn * 128 / 4) / 256, 256>>>();
    k_scatter_uv<<<(EE * 32) / 256, 256>>>(ei);
    k_z<<<(Nn * LL) / 256, 256>>>(gn, bmu, bsig);

    k_zzt<<<dim3(Nn / 128, Nn / 128), 256>>>(out);
}

// round 3
// speedup vs baseline: 1.1118x; 1.1118x over previous
#include <cuda_runtime.h>
#include <cuda_bf16.h>
#include <cstdint>

// Problem constants
#define Nn  8192
#define FIN 512
#define HH  256
#define LL  64
#define EE  262144

// Scratch (device globals; no allocation allowed)
__device__ float g_deg[Nn];
__device__ float g_dinv[Nn];
__device__ float g_xw1[Nn * HH];     // x @ W1
__device__ float g_h[Nn * HH];       // acc then relu'd hidden
__device__ float g_uv[Nn * 128];     // [h@Wmu | h@Wsig]
__device__ float g_uvagg[Nn * 128];  // aggregated heads
__device__ __nv_bfloat16 g_za[Nn * 192];  // [hi | hi | lo]
__device__ __nv_bfloat16 g_zb[Nn * 192];  // [hi | lo | hi]

__device__ __forceinline__ float sigf(float x) {
    return 1.0f / (1.0f + __expf(-x));
}

// ---------------- degree / dinv ----------------
__global__ void k_zero_deg() {
    int i = blockIdx.x * blockDim.x + threadIdx.x;
    if (i < Nn) g_deg[i] = 0.f;
}

__global__ void k_deg(const int* __restrict__ ei) {
    int e = blockIdx.x * blockDim.x + threadIdx.x;
    if (e < EE) atomicAdd(&g_deg[ei[EE + e]], 1.0f);
}

__global__ void k_dinv() {
    int i = blockIdx.x * blockDim.x + threadIdx.x;
    if (i < Nn) g_dinv[i] = rsqrtf(g_deg[i] + 1.0f);
}

// ---------------- GEMM1: g_xw1 = x @ W1  (8192x512x256) ----------------
__global__ __launch_bounds__(256, 2) void k_gemm1(const float* __restrict__ A,
                                                  const float* __restrict__ B) {
    __shared__ float As[32][128];
    __shared__ float Bs[32][128];
    int tid = threadIdx.x;
    int n0 = blockIdx.x * 128, m0 = blockIdx.y * 128;
    int tx = tid & 15, ty = tid >> 4;
    float acc[8][8] = {};

    for (int kt = 0; kt < FIN; kt += 32) {
#pragma unroll
        for (int i = 0; i < 4; i++) {
            int v = i * 256 + tid;
            int m = v & 127, kq = v >> 7;
            float4 f = *(const float4*)(A + (size_t)(m0 + m) * FIN + kt + kq * 4);
            As[kq * 4 + 0][m] = f.x; As[kq * 4 + 1][m] = f.y;
            As[kq * 4 + 2][m] = f.z; As[kq * 4 + 3][m] = f.w;
        }
#pragma unroll
        for (int i = 0; i < 4; i++) {
            int v = i * 256 + tid;
            int kk = v >> 5, n4 = (v & 31) * 4;
            *(float4*)&Bs[kk][n4] =
                *(const float4*)(B + (size_t)(kt + kk) * HH + n0 + n4);
        }
        __syncthreads();
#pragma unroll
        for (int kk = 0; kk < 32; kk++) {
            float a[8], b[8];
            *(float4*)(a)     = *(float4*)&As[kk][ty * 8];
            *(float4*)(a + 4) = *(float4*)&As[kk][ty * 8 + 4];
            *(float4*)(b)     = *(float4*)&Bs[kk][tx * 8];
            *(float4*)(b + 4) = *(float4*)&Bs[kk][tx * 8 + 4];
#pragma unroll
            for (int r = 0; r < 8; r++)
#pragma unroll
                for (int c = 0; c < 8; c++) acc[r][c] += a[r] * b[c];
        }
        __syncthreads();
    }
#pragma unroll
    for (int r = 0; r < 8; r++) {
        int gm = m0 + ty * 8 + r;
        *(float4*)(g_xw1 + (size_t)gm * HH + n0 + tx * 8)     = *(float4*)&acc[r][0];
        *(float4*)(g_xw1 + (size_t)gm * HH + n0 + tx * 8 + 4) = *(float4*)&acc[r][4];
    }
}

// ---------------- aggregation layer 1 ----------------
__global__ void k_init_acc1() {
    int t4 = blockIdx.x * blockDim.x + threadIdx.x;  // float4 index
    if (t4 < Nn * HH / 4) {
        int node = t4 >> 6;  // 64 float4 per row
        float d = g_dinv[node];
        float d2 = d * d;
        float4 v = *((const float4*)g_xw1 + t4);
        v.x *= d2; v.y *= d2; v.z *= d2; v.w *= d2;
        *((float4*)g_h + t4) = v;
    }
}

__global__ void k_scatter_h(const int* __restrict__ ei) {
    int gt = blockIdx.x * blockDim.x + threadIdx.x;
    int w = gt >> 5, lane = gt & 31;
    if (w >= EE) return;
    int src = ei[w], dst = ei[EE + w];
    float norm = g_dinv[src] * g_dinv[dst];
    const float4* s4 = (const float4*)(g_xw1 + (size_t)src * HH);
    float* d = g_h + (size_t)dst * HH;
#pragma unroll
    for (int j = 0; j < 2; j++) {
        int idx = lane + j * 32;
        float4 v = s4[idx];
        atomicAdd(d + idx * 4 + 0, v.x * norm);
        atomicAdd(d + idx * 4 + 1, v.y * norm);
        atomicAdd(d + idx * 4 + 2, v.z * norm);
        atomicAdd(d + idx * 4 + 3, v.w * norm);
    }
}

__global__ void k_finalize_h(const float* __restrict__ b1) {
    int t = blockIdx.x * blockDim.x + threadIdx.x;
    if (t < Nn * HH) {
        float v = g_h[t] + b1[t & 255];
        g_h[t] = v > 0.f ? v : 0.f;
    }
}

// ------------- heads GEMM: g_uv = h @ [Wmu|Wsig]  (8192x256x128) -------------
__global__ __launch_bounds__(256, 2) void k_heads(const float* __restrict__ Wmu,
                                                  const float* __restrict__ Wsig) {
    __shared__ float As[32][128];
    __shared__ float Bs[32][128];
    int tid = threadIdx.x;
    int m0 = blockIdx.y * 128;
    int tx = tid & 15, ty = tid >> 4;
    float acc[8][8] = {};

    for (int kt = 0; kt < HH; kt += 32) {
#pragma unroll
        for (int i = 0; i < 4; i++) {
            int v = i * 256 + tid;
            int m = v & 127, kq = v >> 7;
            float4 f = *(const float4*)(g_h + (size_t)(m0 + m) * HH + kt + kq * 4);
            As[kq * 4 + 0][m] = f.x; As[kq * 4 + 1][m] = f.y;
            As[kq * 4 + 2][m] = f.z; As[kq * 4 + 3][m] = f.w;
        }
#pragma unroll
        for (int i = 0; i < 4; i++) {
            int v = i * 256 + tid;
            int kk = v >> 5, n4 = (v & 31) * 4;
            const float* Bp = (n4 < 64)
                ? (Wmu + (size_t)(kt + kk) * 64 + n4)
                : (Wsig + (size_t)(kt + kk) * 64 + (n4 - 64));
            *(float4*)&Bs[kk][n4] = *(const float4*)Bp;
        }
        __syncthreads();
#pragma unroll
        for (int kk = 0; kk < 32; kk++) {
            float a[8], b[8];
            *(float4*)(a)     = *(float4*)&As[kk][ty * 8];
            *(float4*)(a + 4) = *(float4*)&As[kk][ty * 8 + 4];
            *(float4*)(b)     = *(float4*)&Bs[kk][tx * 8];
            *(float4*)(b + 4) = *(float4*)&Bs[kk][tx * 8 + 4];
#pragma unroll
            for (int r = 0; r < 8; r++)
#pragma unroll
                for (int c = 0; c < 8; c++) acc[r][c] += a[r] * b[c];
        }
        __syncthreads();
    }
#pragma unroll
    for (int r = 0; r < 8; r++) {
        int gm = m0 + ty * 8 + r;
        *(float4*)(g_uv + (size_t)gm * 128 + tx * 8)     = *(float4*)&acc[r][0];
        *(float4*)(g_uv + (size_t)gm * 128 + tx * 8 + 4) = *(float4*)&acc[r][4];
    }
}

// ---------------- aggregation layer 2 (both heads at once) ----------------
__global__ void k_init_acc2() {
    int t4 = blockIdx.x * blockDim.x + threadIdx.x;  // float4 index over Nn*128
    if (t4 < Nn * 128 / 4) {
        int node = t4 >> 5;  // 32 float4 per row
        float d = g_dinv[node];
        float d2 = d * d;
        float4 v = *((const float4*)g_uv + t4);
        v.x *= d2; v.y *= d2; v.z *= d2; v.w *= d2;
        *((float4*)g_uvagg + t4) = v;
    }
}

__global__ void k_scatter_uv(const int* __restrict__ ei) {
    int gt = blockIdx.x * blockDim.x + threadIdx.x;
    int w = gt >> 5, lane = gt & 31;
    if (w >= EE) return;
    int src = ei[w], dst = ei[EE + w];
    float norm = g_dinv[src] * g_dinv[dst];
    const float4* s4 = (const float4*)(g_uv + (size_t)src * 128);
    float* d = g_uvagg + (size_t)dst * 128;
    float4 v = s4[lane];
    atomicAdd(d + lane * 4 + 0, v.x * norm);
    atomicAdd(d + lane * 4 + 1, v.y * norm);
    atomicAdd(d + lane * 4 + 2, v.z * norm);
    atomicAdd(d + lane * 4 + 3, v.w * norm);
}

// ------- z = gnoise*exp(xu)+xs, split into bf16 hi/lo extended rows -------
__global__ void k_z2(const float* __restrict__ gn, const float* __restrict__ bmu,
                     const float* __restrict__ bsig) {
    int t = blockIdx.x * blockDim.x + threadIdx.x;
    if (t < Nn * LL) {
        int node = t >> 6, l = t & 63;
        float u = g_uvagg[(size_t)node * 128 + l] + bmu[l];
        float s = g_uvagg[(size_t)node * 128 + 64 + l] + bsig[l];
        float z = gn[t] * expf(u) + s;
        __nv_bfloat16 hi = __float2bfloat16_rn(z);
        __nv_bfloat16 lo = __float2bfloat16_rn(z - __bfloat162float(hi));
        size_t r = (size_t)node * 192;
        g_za[r + l] = hi;  g_za[r + 64 + l] = hi;  g_za[r + 128 + l] = lo;
        g_zb[r + l] = hi;  g_zb[r + 64 + l] = lo;  g_zb[r + 128 + l] = hi;
    }
}

// ---------------- out = sigmoid(z @ z^T) via bf16 tensor cores ----------------
// D = Aext @ Bext^T, K=192: hi*hi + hi*lo + lo*hi  (fp32 accumulate)
#define PITCH_W 100   // smem row pitch in 32-bit words (400 B, conflict-free)

__device__ __forceinline__ void mma16816(float* d, uint32_t a0, uint32_t a1,
                                         uint32_t a2, uint32_t a3,
                                         uint32_t b0, uint32_t b1) {
    asm volatile(
        "mma.sync.aligned.m16n8k16.row.col.f32.bf16.bf16.f32 "
        "{%0,%1,%2,%3}, {%4,%5,%6,%7}, {%8,%9}, {%0,%1,%2,%3};"
        : "+f"(d[0]), "+f"(d[1]), "+f"(d[2]), "+f"(d[3])
        : "r"(a0), "r"(a1), "r"(a2), "r"(a3), "r"(b0), "r"(b1));
}

__device__ __forceinline__ void ldmx4(uint32_t& r0, uint32_t& r1, uint32_t& r2,
                                      uint32_t& r3, uint32_t addr) {
    asm volatile("ldmatrix.sync.aligned.m8n8.x4.shared.b16 {%0,%1,%2,%3}, [%4];"
                 : "=r"(r0), "=r"(r1), "=r"(r2), "=r"(r3) : "r"(addr));
}

__global__ __launch_bounds__(256, 2) void k_zzt_tc(float* __restrict__ out) {
    extern __shared__ uint32_t smw[];          // A: 128*100 words, B: 128*100 words
    uint32_t* sB = smw + 128 * PITCH_W;
    int tid = threadIdx.x;
    int m0 = blockIdx.y * 128, n0 = blockIdx.x * 128;

    // load A tile (128 x 192 bf16 -> 24 float4 per row)
    for (int i = tid; i < 128 * 24; i += 256) {
        int r = i / 24, f4 = i % 24;
        uint4 v = *((const uint4*)(g_za + (size_t)(m0 + r) * 192) + f4);
        *(uint4*)(smw + r * PITCH_W + f4 * 4) = v;
    }
    // load B tile
    for (int i = tid; i < 128 * 24; i += 256) {
        int r = i / 24, f4 = i % 24;
        uint4 v = *((const uint4*)(g_zb + (size_t)(n0 + r) * 192) + f4);
        *(uint4*)(sB + r * PITCH_W + f4 * 4) = v;
    }
    __syncthreads();

    int w = tid >> 5, lane = tid & 31;
    int wm = (w & 3) * 32;       // warp m band (32 rows)
    int wn = (w >> 2) * 64;      // warp n band (64 cols)
    int lr = lane & 15, lc = lane >> 4;

    uint32_t baseA = (uint32_t)__cvta_generic_to_shared(smw);
    uint32_t baseB = (uint32_t)__cvta_generic_to_shared(sB);

    float acc[2][8][4];
#pragma unroll
    for (int a = 0; a < 2; a++)
#pragma unroll
        for (int b = 0; b < 8; b++)
#pragma unroll
            for (int c = 0; c < 4; c++) acc[a][b][c] = 0.f;

    for (int ks = 0; ks < 12; ks++) {
        uint32_t a0[2], a1[2], a2[2], a3[2];
#pragma unroll
        for (int mi = 0; mi < 2; mi++) {
            uint32_t ad = baseA + (uint32_t)(wm + mi * 16 + lr) * 400 + ks * 32 + lc * 16;
            ldmx4(a0[mi], a1[mi], a2[mi], a3[mi], ad);
        }
#pragma unroll
        for (int ni = 0; ni < 4; ni++) {
            uint32_t b0, b1, b2, b3;
            uint32_t bd = baseB + (uint32_t)(wn + ni * 16 + lr) * 400 + ks * 32 + lc * 16;
            ldmx4(b0, b1, b2, b3, bd);
#pragma unroll
            for (int mi = 0; mi < 2; mi++) {
                mma16816(acc[mi][ni * 2 + 0], a0[mi], a1[mi], a2[mi], a3[mi], b0, b2);
                mma16816(acc[mi][ni * 2 + 1], a0[mi], a1[mi], a2[mi], a3[mi], b1, b3);
            }
        }
    }

    // epilogue: sigmoid + store
    int tr = lane >> 2, tc = (lane & 3) * 2;
#pragma unroll
    for (int mi = 0; mi < 2; mi++) {
#pragma unroll
        for (int nj = 0; nj < 8; nj++) {
            int gr = m0 + wm + mi * 16 + tr;
            int gc = n0 + wn + nj * 8 + tc;
            float2 v0, v1;
            v0.x = sigf(acc[mi][nj][0]); v0.y = sigf(acc[mi][nj][1]);
            v1.x = sigf(acc[mi][nj][2]); v1.y = sigf(acc[mi][nj][3]);
            *(float2*)(out + (size_t)gr * Nn + gc)       = v0;
            *(float2*)(out + (size_t)(gr + 8) * Nn + gc) = v1;
        }
    }
}

// ---------------- launch ----------------
extern "C" void kernel_launch(void* const* d_in, const int* in_sizes, int n_in,
                              void* d_out, int out_size) {
    const float* x    = (const float*)d_in[0];
    const int*   ei   = (const int*)d_in[1];
    const float* W1   = (const float*)d_in[2];
    const float* b1   = (const float*)d_in[3];
    const float* Wmu  = (const float*)d_in[4];
    const float* bmu  = (const float*)d_in[5];
    const float* Wsig = (const float*)d_in[6];
    const float* bsig = (const float*)d_in[7];
    const float* gn   = (const float*)d_in[8];
    float* out = (float*)d_out;
    (void)in_sizes; (void)n_in; (void)out_size;

    cudaFuncSetAttribute(k_zzt_tc, cudaFuncAttributeMaxDynamicSharedMemorySize,
                         2 * 128 * PITCH_W * 4);

    k_zero_deg<<<Nn / 256, 256>>>();
    k_deg<<<EE / 256, 256>>>(ei);
    k_dinv<<<Nn / 256, 256>>>();

    k_gemm1<<<dim3(HH / 128, Nn / 128), 256>>>(x, W1);
    k_init_acc1<<<(Nn * HH / 4) / 256, 256>>>();
    k_scatter_h<<<(EE * 32) / 256, 256>>>(ei);
    k_finalize_h<<<(Nn * HH) / 256, 256>>>(b1);

    k_heads<<<dim3(1, Nn / 128), 256>>>(Wmu, Wsig);
    k_init_acc2<<<(Nn * 128 / 4) / 256, 256>>>();
    k_scatter_uv<<<(EE * 32) / 256, 256>>>(ei);
    k_z2<<<(Nn * LL) / 256, 256>>>(gn, bmu, bsig);

    k_zzt_tc<<<dim3(Nn / 128, Nn / 128), 256, 2 * 128 * PITCH_W * 4>>>(out);
}

// round 6
// speedup vs baseline: 1.1936x; 1.0735x over previous
#include <cuda_runtime.h>
#include <cuda_bf16.h>
#include <cstdint>

// Problem constants
#define Nn  8192
#define FIN 512
#define HH  256
#define LL  64
#define EE  262144

typedef __nv_bfloat16 bf16;

// Scratch (device globals; no allocation allowed)
__device__ float g_deg[Nn];
__device__ float g_dinv[Nn];
__device__ float g_xw1[Nn * HH];     // x @ W1 (fp32)
__device__ float g_h[Nn * HH];       // acc then relu'd hidden
__device__ float g_uv[Nn * 128];     // [h@Wmu | h@Wsig]
__device__ float g_uvagg[Nn * 128];  // aggregated heads
__device__ bf16  g_za[Nn * 192];     // [hi | hi | lo]
__device__ bf16  g_zb[Nn * 192];     // [hi | lo | hi]
// bf16 split operands
__device__ bf16 g_xhi[Nn * FIN];
__device__ bf16 g_xlo[Nn * FIN];
__device__ bf16 g_w1thi[HH * FIN];   // W1^T [256][512]
__device__ bf16 g_w1tlo[HH * FIN];
__device__ bf16 g_hhi[Nn * HH];
__device__ bf16 g_hlo[Nn * HH];
__device__ bf16 g_whthi[128 * HH];   // [Wmu|Wsig]^T [128][256]
__device__ bf16 g_whtlo[128 * HH];

__device__ __forceinline__ float sigf(float x) {
    return 1.0f / (1.0f + __expf(-x));
}

// ---------------- degree / dinv ----------------
__global__ void k_zero_deg() {
    int i = blockIdx.x * blockDim.x + threadIdx.x;
    if (i < Nn) g_deg[i] = 0.f;
}
__global__ void k_deg(const int* __restrict__ ei) {
    int e = blockIdx.x * blockDim.x + threadIdx.x;
    if (e < EE) atomicAdd(&g_deg[ei[EE + e]], 1.0f);
}
__global__ void k_dinv() {
    int i = blockIdx.x * blockDim.x + threadIdx.x;
    if (i < Nn) g_dinv[i] = rsqrtf(g_deg[i] + 1.0f);
}

// ---------------- bf16 hi/lo splits (device-global outputs only) -----------
__device__ __forceinline__ void split_store(bf16* hi, bf16* lo, int i4, float4 v) {
    bf16 h0 = __float2bfloat16_rn(v.x), h1 = __float2bfloat16_rn(v.y);
    bf16 h2 = __float2bfloat16_rn(v.z), h3 = __float2bfloat16_rn(v.w);
    bf16 l0 = __float2bfloat16_rn(v.x - __bfloat162float(h0));
    bf16 l1 = __float2bfloat16_rn(v.y - __bfloat162float(h1));
    bf16 l2 = __float2bfloat16_rn(v.z - __bfloat162float(h2));
    bf16 l3 = __float2bfloat16_rn(v.w - __bfloat162float(h3));
    __nv_bfloat162* hp = (__nv_bfloat162*)(hi + (size_t)i4 * 4);
    __nv_bfloat162* lp = (__nv_bfloat162*)(lo + (size_t)i4 * 4);
    hp[0] = __nv_bfloat162(h0, h1);
    hp[1] = __nv_bfloat162(h2, h3);
    lp[0] = __nv_bfloat162(l0, l1);
    lp[1] = __nv_bfloat162(l2, l3);
}

__global__ void k_split_x(const float* __restrict__ x) {
    int i = blockIdx.x * blockDim.x + threadIdx.x;
    if (i < Nn * FIN / 4) split_store(g_xhi, g_xlo, i, *((const float4*)x + i));
}

__global__ void k_split_h() {
    int i = blockIdx.x * blockDim.x + threadIdx.x;
    if (i < Nn * HH / 4) split_store(g_hhi, g_hlo, i, *((const float4*)g_h + i));
}

// W1 [512][256] -> transposed split [256][512]
__global__ void k_split_w1t(const float* __restrict__ W) {
    int t = blockIdx.x * blockDim.x + threadIdx.x;  // over 512*256
    if (t < FIN * HH) {
        int k = t / HH, n = t % HH;
        float v = W[t];
        bf16 h = __float2bfloat16_rn(v);
        bf16 l = __float2bfloat16_rn(v - __bfloat162float(h));
        g_w1thi[(size_t)n * FIN + k] = h;
        g_w1tlo[(size_t)n * FIN + k] = l;
    }
}

// [Wmu|Wsig] -> transposed split [128][256]
__global__ void k_split_wht(const float* __restrict__ Wmu,
                            const float* __restrict__ Wsig) {
    int t = blockIdx.x * blockDim.x + threadIdx.x;  // over 256*128
    if (t < HH * 128) {
        int k = t / 128, n = t % 128;
        float v = (n < 64) ? Wmu[(size_t)k * 64 + n] : Wsig[(size_t)k * 64 + (n - 64)];
        bf16 h = __float2bfloat16_rn(v);
        bf16 l = __float2bfloat16_rn(v - __bfloat162float(h));
        g_whthi[(size_t)n * HH + k] = h;
        g_whtlo[(size_t)n * HH + k] = l;
    }
}

// ---------------- tensor-core GEMM (hi/lo split, A[M][K] x B[N][K]^T) ------
#define KT   128                  // k-tile (bf16 elems)
#define TPW  68                   // smem pitch words (272 B)

__device__ __forceinline__ void mma16816(float* d, uint32_t a0, uint32_t a1,
                                         uint32_t a2, uint32_t a3,
                                         uint32_t b0, uint32_t b1) {
    asm volatile(
        "mma.sync.aligned.m16n8k16.row.col.f32.bf16.bf16.f32 "
        "{%0,%1,%2,%3}, {%4,%5,%6,%7}, {%8,%9}, {%0,%1,%2,%3};"
        : "+f"(d[0]), "+f"(d[1]), "+f"(d[2]), "+f"(d[3])
        : "r"(a0), "r"(a1), "r"(a2), "r"(a3), "r"(b0), "r"(b1));
}
__device__ __forceinline__ void ldmx4(uint32_t& r0, uint32_t& r1, uint32_t& r2,
                                      uint32_t& r3, uint32_t addr) {
    asm volatile("ldmatrix.sync.aligned.m8n8.x4.shared.b16 {%0,%1,%2,%3}, [%4];"
                 : "=r"(r0), "=r"(r1), "=r"(r2), "=r"(r3) : "r"(addr));
}

// MODE 0: A=g_x(512), B=g_w1t -> g_xw1(w=256) + g_h=v*d2, 128-row tiles
// MODE 1: A=g_h(256),  B=g_wht -> g_uv(w=128) + g_uvagg=v*d2, 64-row tiles
template <int MODE>
__global__ __launch_bounds__(256) void k_gemm_tc() {
    constexpr int MI = (MODE == 0) ? 2 : 1;
    constexpr int K  = (MODE == 0) ? FIN : HH;
    constexpr int MT = 64 * MI;
    const bf16* Ahi = (MODE == 0) ? g_xhi : g_hhi;
    const bf16* Alo = (MODE == 0) ? g_xlo : g_hlo;
    const bf16* Bhi = (MODE == 0) ? g_w1thi : g_whthi;
    const bf16* Blo = (MODE == 0) ? g_w1tlo : g_whtlo;

    extern __shared__ uint32_t smw[];
    uint32_t* sB = smw + MT * TPW;
    int tid = threadIdx.x;
    int m0 = blockIdx.y * MT, n0 = blockIdx.x * 128;

    int w = tid >> 5, lane = tid & 31;
    int wm = (w & 3) * 16 * MI;
    int wn = (w >> 2) * 64;
    int lr = lane & 15, lc = lane >> 4;
    uint32_t baseA = (uint32_t)__cvta_generic_to_shared(smw);
    uint32_t baseB = (uint32_t)__cvta_generic_to_shared(sB);

    float acc[MI][8][4];
#pragma unroll
    for (int a = 0; a < MI; a++)
#pragma unroll
        for (int b = 0; b < 8; b++)
#pragma unroll
            for (int c = 0; c < 4; c++) acc[a][b][c] = 0.f;

    const bf16* pa[3] = {Ahi, Ahi, Alo};
    const bf16* pb[3] = {Bhi, Blo, Bhi};

    for (int ph = 0; ph < 3; ph++) {
        const bf16* A = pa[ph];
        const bf16* B = pb[ph];
        for (int kt = 0; kt < K; kt += KT) {
            for (int i = tid; i < MT * 16; i += 256) {
                int r = i >> 4, q = i & 15;
                uint4 v = *(const uint4*)(A + (size_t)(m0 + r) * K + kt + q * 8);
                *(uint4*)(smw + r * TPW + q * 4) = v;
            }
            for (int i = tid; i < 128 * 16; i += 256) {
                int r = i >> 4, q = i & 15;
                uint4 v = *(const uint4*)(B + (size_t)(n0 + r) * K + kt + q * 8);
                *(uint4*)(sB + r * TPW + q * 4) = v;
            }
            __syncthreads();
#pragma unroll
            for (int ks = 0; ks < KT / 16; ks++) {
                uint32_t a0[MI], a1[MI], a2[MI], a3[MI];
#pragma unroll
                for (int mi = 0; mi < MI; mi++) {
                    uint32_t ad = baseA + (uint32_t)(wm + mi * 16 + lr) * (TPW * 4)
                                + ks * 32 + lc * 16;
                    ldmx4(a0[mi], a1[mi], a2[mi], a3[mi], ad);
                }
#pragma unroll
                for (int ni = 0; ni < 4; ni++) {
                    uint32_t b0, b1, b2, b3;
                    uint32_t bd = baseB + (uint32_t)(wn + ni * 16 + lr) * (TPW * 4)
                                + ks * 32 + lc * 16;
                    ldmx4(b0, b1, b2, b3, bd);
#pragma unroll
                    for (int mi = 0; mi < MI; mi++) {
                        mma16816(acc[mi][ni * 2 + 0], a0[mi], a1[mi], a2[mi], a3[mi], b0, b2);
                        mma16816(acc[mi][ni * 2 + 1], a0[mi], a1[mi], a2[mi], a3[mi], b1, b3);
                    }
                }
            }
            __syncthreads();
        }
    }

    // epilogue (device-global outputs referenced from device code)
    int tr = lane >> 2, tc = (lane & 3) * 2;
    constexpr int wout = (MODE == 0) ? 256 : 128;
    float* out1 = (MODE == 0) ? g_xw1 : g_uv;
    float* out2 = (MODE == 0) ? g_h : g_uvagg;
#pragma unroll
    for (int mi = 0; mi < MI; mi++) {
#pragma unroll
        for (int half = 0; half < 2; half++) {
            int gr = m0 + wm + mi * 16 + tr + half * 8;
            float dv = g_dinv[gr];
            float d2 = dv * dv;
#pragma unroll
            for (int nj = 0; nj < 8; nj++) {
                int gc = n0 + wn + nj * 8 + tc;
                float v0 = acc[mi][nj][half * 2 + 0];
                float v1 = acc[mi][nj][half * 2 + 1];
                float2 o = {v0, v1};
                float2 s = {v0 * d2, v1 * d2};
                *(float2*)(out1 + (size_t)gr * wout + gc) = o;
                *(float2*)(out2 + (size_t)gr * wout + gc) = s;
            }
        }
    }
}

// ---------------- scatters (proven scalar atomics) ----------------
__global__ void k_scatter_h(const int* __restrict__ ei) {
    int gt = blockIdx.x * blockDim.x + threadIdx.x;
    int w = gt >> 5, lane = gt & 31;
    if (w >= EE) return;
    int src = ei[w], dst = ei[EE + w];
    float norm = g_dinv[src] * g_dinv[dst];
    const float4* s4 = (const float4*)(g_xw1 + (size_t)src * HH);
    float* d = g_h + (size_t)dst * HH;
#pragma unroll
    for (int j = 0; j < 2; j++) {
        int idx = lane + j * 32;
        float4 v = s4[idx];
        atomicAdd(d + idx * 4 + 0, v.x * norm);
        atomicAdd(d + idx * 4 + 1, v.y * norm);
        atomicAdd(d + idx * 4 + 2, v.z * norm);
        atomicAdd(d + idx * 4 + 3, v.w * norm);
    }
}

__global__ void k_finalize_h(const float* __restrict__ b1) {
    int t = blockIdx.x * blockDim.x + threadIdx.x;
    if (t < Nn * HH) {
        float v = g_h[t] + b1[t & 255];
        g_h[t] = v > 0.f ? v : 0.f;
    }
}

__global__ void k_scatter_uv(const int* __restrict__ ei) {
    int gt = blockIdx.x * blockDim.x + threadIdx.x;
    int w = gt >> 5, lane = gt & 31;
    if (w >= EE) return;
    int src = ei[w], dst = ei[EE + w];
    float norm = g_dinv[src] * g_dinv[dst];
    const float4* s4 = (const float4*)(g_uv + (size_t)src * 128);
    float* d = g_uvagg + (size_t)dst * 128;
    float4 v = s4[lane];
    atomicAdd(d + lane * 4 + 0, v.x * norm);
    atomicAdd(d + lane * 4 + 1, v.y * norm);
    atomicAdd(d + lane * 4 + 2, v.z * norm);
    atomicAdd(d + lane * 4 + 3, v.w * norm);
}

// ------- z = gnoise*exp(xu)+xs, split into bf16 hi/lo extended rows -------
__global__ void k_z2(const float* __restrict__ gn, const float* __restrict__ bmu,
                     const float* __restrict__ bsig) {
    int t = blockIdx.x * blockDim.x + threadIdx.x;
    if (t < Nn * LL) {
        int node = t >> 6, l = t & 63;
        float u = g_uvagg[(size_t)node * 128 + l] + bmu[l];
        float s = g_uvagg[(size_t)node * 128 + 64 + l] + bsig[l];
        float z = gn[t] * expf(u) + s;
        bf16 hi = __float2bfloat16_rn(z);
        bf16 lo = __float2bfloat16_rn(z - __bfloat162float(hi));
        size_t r = (size_t)node * 192;
        g_za[r + l] = hi;  g_za[r + 64 + l] = hi;  g_za[r + 128 + l] = lo;
        g_zb[r + l] = hi;  g_zb[r + 64 + l] = lo;  g_zb[r + 128 + l] = hi;
    }
}

// ---------------- out = sigmoid(z @ z^T) via bf16 tensor cores ----------------
#define PITCH_W 100   // smem row pitch in 32-bit words (400 B)

__global__ __launch_bounds__(256, 2) void k_zzt_tc(float* __restrict__ out) {
    extern __shared__ uint32_t smw[];
    uint32_t* sB = smw + 128 * PITCH_W;
    int tid = threadIdx.x;
    int m0 = blockIdx.y * 128, n0 = blockIdx.x * 128;

    for (int i = tid; i < 128 * 24; i += 256) {
        int r = i / 24, f4 = i % 24;
        uint4 v = *((const uint4*)(g_za + (size_t)(m0 + r) * 192) + f4);
        *(uint4*)(smw + r * PITCH_W + f4 * 4) = v;
    }
    for (int i = tid; i < 128 * 24; i += 256) {
        int r = i / 24, f4 = i % 24;
        uint4 v = *((const uint4*)(g_zb + (size_t)(n0 + r) * 192) + f4);
        *(uint4*)(sB + r * PITCH_W + f4 * 4) = v;
    }
    __syncthreads();

    int w = tid >> 5, lane = tid & 31;
    int wm = (w & 3) * 32;
    int wn = (w >> 2) * 64;
    int lr = lane & 15, lc = lane >> 4;
    uint32_t baseA = (uint32_t)__cvta_generic_to_shared(smw);
    uint32_t baseB = (uint32_t)__cvta_generic_to_shared(sB);

    float acc[2][8][4];
#pragma unroll
    for (int a = 0; a < 2; a++)
#pragma unroll
        for (int b = 0; b < 8; b++)
#pragma unroll
            for (int c = 0; c < 4; c++) acc[a][b][c] = 0.f;

    for (int ks = 0; ks < 12; ks++) {
        uint32_t a0[2], a1[2], a2[2], a3[2];
#pragma unroll
        for (int mi = 0; mi < 2; mi++) {
            uint32_t ad = baseA + (uint32_t)(wm + mi * 16 + lr) * 400 + ks * 32 + lc * 16;
            ldmx4(a0[mi], a1[mi], a2[mi], a3[mi], ad);
        }
#pragma unroll
        for (int ni = 0; ni < 4; ni++) {
            uint32_t b0, b1, b2, b3;
            uint32_t bd = baseB + (uint32_t)(wn + ni * 16 + lr) * 400 + ks * 32 + lc * 16;
            ldmx4(b0, b1, b2, b3, bd);
#pragma unroll
            for (int mi = 0; mi < 2; mi++) {
                mma16816(acc[mi][ni * 2 + 0], a0[mi], a1[mi], a2[mi], a3[mi], b0, b2);
                mma16816(acc[mi][ni * 2 + 1], a0[mi], a1[mi], a2[mi], a3[mi], b1, b3);
            }
        }
    }

    int tr = lane >> 2, tc = (lane & 3) * 2;
#pragma unroll
    for (int mi = 0; mi < 2; mi++) {
#pragma unroll
        for (int nj = 0; nj < 8; nj++) {
            int gr = m0 + wm + mi * 16 + tr;
            int gc = n0 + wn + nj * 8 + tc;
            float2 v0, v1;
            v0.x = sigf(acc[mi][nj][0]); v0.y = sigf(acc[mi][nj][1]);
            v1.x = sigf(acc[mi][nj][2]); v1.y = sigf(acc[mi][nj][3]);
            *(float2*)(out + (size_t)gr * Nn + gc)       = v0;
            *(float2*)(out + (size_t)(gr + 8) * Nn + gc) = v1;
        }
    }
}

// ---------------- launch ----------------
extern "C" void kernel_launch(void* const* d_in, const int* in_sizes, int n_in,
                              void* d_out, int out_size) {
    const float* x    = (const float*)d_in[0];
    const int*   ei   = (const int*)d_in[1];
    const float* W1   = (const float*)d_in[2];
    const float* b1   = (const float*)d_in[3];
    const float* Wmu  = (const float*)d_in[4];
    const float* bmu  = (const float*)d_in[5];
    const float* Wsig = (const float*)d_in[6];
    const float* bsig = (const float*)d_in[7];
    const float* gn   = (const float*)d_in[8];
    float* out = (float*)d_out;
    (void)in_sizes; (void)n_in; (void)out_size;

    int smem_g1 = (128 + 128) * TPW * 4;   // 69632
    int smem_g2 = (64 + 128) * TPW * 4;    // 52224
    cudaFuncSetAttribute(k_gemm_tc<0>, cudaFuncAttributeMaxDynamicSharedMemorySize, smem_g1);
    cudaFuncSetAttribute(k_gemm_tc<1>, cudaFuncAttributeMaxDynamicSharedMemorySize, smem_g2);
    cudaFuncSetAttribute(k_zzt_tc, cudaFuncAttributeMaxDynamicSharedMemorySize,
                         2 * 128 * PITCH_W * 4);

    k_zero_deg<<<Nn / 256, 256>>>();
    k_deg<<<EE / 256, 256>>>(ei);
    k_dinv<<<Nn / 256, 256>>>();

    // splits for layer 1
    k_split_x<<<(Nn * FIN / 4 + 255) / 256, 256>>>(x);
    k_split_w1t<<<(FIN * HH + 255) / 256, 256>>>(W1);

    // GEMM1 + fused dinv^2 pre-accumulation
    k_gemm_tc<0><<<dim3(2, 64), 256, smem_g1>>>();
    k_scatter_h<<<(EE * 32) / 256, 256>>>(ei);
    k_finalize_h<<<(Nn * HH) / 256, 256>>>(b1);

    // splits for layer 2
    k_split_h<<<(Nn * HH / 4 + 255) / 256, 256>>>();
    k_split_wht<<<(HH * 128 + 255) / 256, 256>>>(Wmu, Wsig);

    k_gemm_tc<1><<<dim3(1, 128), 256, smem_g2>>>();
    k_scatter_uv<<<(EE * 32) / 256, 256>>>(ei);
    k_z2<<<(Nn * LL) / 256, 256>>>(gn, bmu, bsig);

    k_zzt_tc<<<dim3(Nn / 128, Nn / 128), 256, 2 * 128 * PITCH_W * 4>>>(out);
}

// round 8
// speedup vs baseline: 1.7326x; 1.4516x over previous
#include <cuda_runtime.h>
#include <cuda_bf16.h>
#include <cstdint>

// Problem constants
#define Nn  8192
#define FIN 512
#define HH  256
#define LL  64
#define EE  262144

typedef __nv_bfloat16 bf16;

// Scratch (device globals; no allocation allowed)
__device__ int   g_cnt[Nn];
__device__ int   g_off[Nn + 1];
__device__ int   g_cur[Nn];
__device__ int   g_csr_src[EE];
__device__ float g_csr_w[EE];
__device__ float g_dinv[Nn];
__device__ float g_xw1[Nn * HH];     // x @ W1 (fp32)
__device__ float g_uv[Nn * 128];     // [h@Wmu | h@Wsig]
__device__ bf16  g_za[Nn * 192];     // [hi | hi | lo]
__device__ bf16  g_zb[Nn * 192];     // [hi | lo | hi]
// bf16 split operands
__device__ bf16 g_xhi[Nn * FIN];
__device__ bf16 g_xlo[Nn * FIN];
__device__ bf16 g_w1thi[HH * FIN];   // W1^T [256][512]
__device__ bf16 g_w1tlo[HH * FIN];
__device__ bf16 g_hhi[Nn * HH];
__device__ bf16 g_hlo[Nn * HH];
__device__ bf16 g_whthi[128 * HH];   // [Wmu|Wsig]^T [128][256]
__device__ bf16 g_whtlo[128 * HH];

__device__ __forceinline__ float sigf(float x) {
    return 1.0f / (1.0f + __expf(-x));
}

// ---------------- CSR build ----------------
__global__ void k_zero_cnt() {
    int i = blockIdx.x * blockDim.x + threadIdx.x;
    if (i < Nn) g_cnt[i] = 0;
}
__global__ void k_deg_i(const int* __restrict__ ei) {
    int e = blockIdx.x * blockDim.x + threadIdx.x;
    if (e < EE) atomicAdd(&g_cnt[ei[EE + e]], 1);
}
// single-block scan over 8192 counts; also dinv
__global__ void k_scan() {
    __shared__ int ssum[256];
    int t = threadIdx.x;
    int base = t * 32;
    int s = 0;
#pragma unroll
    for (int i = 0; i < 32; i++) s += g_cnt[base + i];
    ssum[t] = s;
    __syncthreads();
    if (t == 0) {
        int run = 0;
        for (int i = 0; i < 256; i++) { int v = ssum[i]; ssum[i] = run; run += v; }
        g_off[Nn] = run;
    }
    __syncthreads();
    int run = ssum[t];
#pragma unroll
    for (int i = 0; i < 32; i++) {
        int c = g_cnt[base + i];
        g_off[base + i] = run;
        g_cur[base + i] = run;
        g_dinv[base + i] = rsqrtf((float)c + 1.0f);
        run += c;
    }
}
__global__ void k_fill(const int* __restrict__ ei) {
    int e = blockIdx.x * blockDim.x + threadIdx.x;
    if (e < EE) {
        int src = ei[e], dst = ei[EE + e];
        int pos = atomicAdd(&g_cur[dst], 1);
        g_csr_src[pos] = src;
        g_csr_w[pos] = g_dinv[src] * g_dinv[dst];
    }
}

// ---------------- bf16 hi/lo splits ----------------
__device__ __forceinline__ void split_store(bf16* hi, bf16* lo, int i4, float4 v) {
    bf16 h0 = __float2bfloat16_rn(v.x), h1 = __float2bfloat16_rn(v.y);
    bf16 h2 = __float2bfloat16_rn(v.z), h3 = __float2bfloat16_rn(v.w);
    bf16 l0 = __float2bfloat16_rn(v.x - __bfloat162float(h0));
    bf16 l1 = __float2bfloat16_rn(v.y - __bfloat162float(h1));
    bf16 l2 = __float2bfloat16_rn(v.z - __bfloat162float(h2));
    bf16 l3 = __float2bfloat16_rn(v.w - __bfloat162float(h3));
    __nv_bfloat162* hp = (__nv_bfloat162*)(hi + (size_t)i4 * 4);
    __nv_bfloat162* lp = (__nv_bfloat162*)(lo + (size_t)i4 * 4);
    hp[0] = __nv_bfloat162(h0, h1);
    hp[1] = __nv_bfloat162(h2, h3);
    lp[0] = __nv_bfloat162(l0, l1);
    lp[1] = __nv_bfloat162(l2, l3);
}

__global__ void k_split_x(const float* __restrict__ x) {
    int i = blockIdx.x * blockDim.x + threadIdx.x;
    if (i < Nn * FIN / 4) split_store(g_xhi, g_xlo, i, *((const float4*)x + i));
}

__global__ void k_split_w1t(const float* __restrict__ W) {
    int t = blockIdx.x * blockDim.x + threadIdx.x;
    if (t < FIN * HH) {
        int k = t / HH, n = t % HH;
        float v = W[t];
        bf16 h = __float2bfloat16_rn(v);
        bf16 l = __float2bfloat16_rn(v - __bfloat162float(h));
        g_w1thi[(size_t)n * FIN + k] = h;
        g_w1tlo[(size_t)n * FIN + k] = l;
    }
}

__global__ void k_split_wht(const float* __restrict__ Wmu,
                            const float* __restrict__ Wsig) {
    int t = blockIdx.x * blockDim.x + threadIdx.x;
    if (t < HH * 128) {
        int k = t / 128, n = t % 128;
        float v = (n < 64) ? Wmu[(size_t)k * 64 + n] : Wsig[(size_t)k * 64 + (n - 64)];
        bf16 h = __float2bfloat16_rn(v);
        bf16 l = __float2bfloat16_rn(v - __bfloat162float(h));
        g_whthi[(size_t)n * HH + k] = h;
        g_whtlo[(size_t)n * HH + k] = l;
    }
}

// ---------------- mma.sync tensor-core GEMM for layers 1/2 ------
#define KT   128                  // k-tile (bf16 elems)
#define TPW  68                   // smem pitch words (272 B)

__device__ __forceinline__ void mma16816(float* d, uint32_t a0, uint32_t a1,
                                         uint32_t a2, uint32_t a3,
                                         uint32_t b0, uint32_t b1) {
    asm volatile(
        "mma.sync.aligned.m16n8k16.row.col.f32.bf16.bf16.f32 "
        "{%0,%1,%2,%3}, {%4,%5,%6,%7}, {%8,%9}, {%0,%1,%2,%3};"
        : "+f"(d[0]), "+f"(d[1]), "+f"(d[2]), "+f"(d[3])
        : "r"(a0), "r"(a1), "r"(a2), "r"(a3), "r"(b0), "r"(b1));
}
__device__ __forceinline__ void ldmx4(uint32_t& r0, uint32_t& r1, uint32_t& r2,
                                      uint32_t& r3, uint32_t addr) {
    asm volatile("ldmatrix.sync.aligned.m8n8.x4.shared.b16 {%0,%1,%2,%3}, [%4];"
                 : "=r"(r0), "=r"(r1), "=r"(r2), "=r"(r3) : "r"(addr));
}

// MODE 0: A=g_x(512), B=g_w1t -> g_xw1 (w=256), 128-row tiles
// MODE 1: A=g_h(256), B=g_wht -> g_uv  (w=128), 64-row tiles
template <int MODE>
__global__ __launch_bounds__(256) void k_gemm_tc() {
    constexpr int MI = (MODE == 0) ? 2 : 1;
    constexpr int K  = (MODE == 0) ? FIN : HH;
    constexpr int MT = 64 * MI;
    const bf16* Ahi = (MODE == 0) ? g_xhi : g_hhi;
    const bf16* Alo = (MODE == 0) ? g_xlo : g_hlo;
    const bf16* Bhi = (MODE == 0) ? g_w1thi : g_whthi;
    const bf16* Blo = (MODE == 0) ? g_w1tlo : g_whtlo;

    extern __shared__ uint32_t smw[];
    uint32_t* sB = smw + MT * TPW;
    int tid = threadIdx.x;
    int m0 = blockIdx.y * MT, n0 = blockIdx.x * 128;

    int w = tid >> 5, lane = tid & 31;
    int wm = (w & 3) * 16 * MI;
    int wn = (w >> 2) * 64;
    int lr = lane & 15, lc = lane >> 4;
    uint32_t baseA = (uint32_t)__cvta_generic_to_shared(smw);
    uint32_t baseB = (uint32_t)__cvta_generic_to_shared(sB);

    float acc[MI][8][4];
#pragma unroll
    for (int a = 0; a < MI; a++)
#pragma unroll
        for (int b = 0; b < 8; b++)
#pragma unroll
            for (int c = 0; c < 4; c++) acc[a][b][c] = 0.f;

    const bf16* pa[3] = {Ahi, Ahi, Alo};
    const bf16* pb[3] = {Bhi, Blo, Bhi};

    for (int ph = 0; ph < 3; ph++) {
        const bf16* A = pa[ph];
        const bf16* B = pb[ph];
        for (int kt = 0; kt < K; kt += KT) {
            for (int i = tid; i < MT * 16; i += 256) {
                int r = i >> 4, q = i & 15;
                uint4 v = *(const uint4*)(A + (size_t)(m0 + r) * K + kt + q * 8);
                *(uint4*)(smw + r * TPW + q * 4) = v;
            }
            for (int i = tid; i < 128 * 16; i += 256) {
                int r = i >> 4, q = i & 15;
                uint4 v = *(const uint4*)(B + (size_t)(n0 + r) * K + kt + q * 8);
                *(uint4*)(sB + r * TPW + q * 4) = v;
            }
            __syncthreads();
#pragma unroll
            for (int ks = 0; ks < KT / 16; ks++) {
                uint32_t a0[MI], a1[MI], a2[MI], a3[MI];
#pragma unroll
                for (int mi = 0; mi < MI; mi++) {
                    uint32_t ad = baseA + (uint32_t)(wm + mi * 16 + lr) * (TPW * 4)
                                + ks * 32 + lc * 16;
                    ldmx4(a0[mi], a1[mi], a2[mi], a3[mi], ad);
                }
#pragma unroll
                for (int ni = 0; ni < 4; ni++) {
                    uint32_t b0, b1, b2, b3;
                    uint32_t bd = baseB + (uint32_t)(wn + ni * 16 + lr) * (TPW * 4)
                                + ks * 32 + lc * 16;
                    ldmx4(b0, b1, b2, b3, bd);
#pragma unroll
                    for (int mi = 0; mi < MI; mi++) {
                        mma16816(acc[mi][ni * 2 + 0], a0[mi], a1[mi], a2[mi], a3[mi], b0, b2);
                        mma16816(acc[mi][ni * 2 + 1], a0[mi], a1[mi], a2[mi], a3[mi], b1, b3);
                    }
                }
            }
            __syncthreads();
        }
    }

    int tr = lane >> 2, tc = (lane & 3) * 2;
    constexpr int wout = (MODE == 0) ? 256 : 128;
    float* out1 = (MODE == 0) ? g_xw1 : g_uv;
#pragma unroll
    for (int mi = 0; mi < MI; mi++) {
#pragma unroll
        for (int half = 0; half < 2; half++) {
            int gr = m0 + wm + mi * 16 + tr + half * 8;
#pragma unroll
            for (int nj = 0; nj < 8; nj++) {
                int gc = n0 + wn + nj * 8 + tc;
                float2 o = {acc[mi][nj][half * 2 + 0], acc[mi][nj][half * 2 + 1]};
                *(float2*)(out1 + (size_t)gr * wout + gc) = o;
            }
        }
    }
}

// ------- gather layer 1: h = relu(sum_e w*xw1[src] + d2*xw1[n] + b1), split -------
__global__ __launch_bounds__(64) void k_gather1(const float* __restrict__ b1) {
    int n = blockIdx.x;
    int t = threadIdx.x;             // 64 threads, each a float4 of the 256-wide row
    float dv = g_dinv[n];
    float d2 = dv * dv;
    float4 acc = *((const float4*)(g_xw1 + (size_t)n * HH) + t);
    acc.x *= d2; acc.y *= d2; acc.z *= d2; acc.w *= d2;
    int e0 = g_off[n], e1 = g_off[n + 1];
    for (int e = e0; e < e1; e++) {
        int src = g_csr_src[e];
        float wgt = g_csr_w[e];
        float4 u = *((const float4*)(g_xw1 + (size_t)src * HH) + t);
        acc.x += u.x * wgt; acc.y += u.y * wgt; acc.z += u.z * wgt; acc.w += u.w * wgt;
    }
    float4 b = ((const float4*)b1)[t];
    acc.x = fmaxf(acc.x + b.x, 0.f);
    acc.y = fmaxf(acc.y + b.y, 0.f);
    acc.z = fmaxf(acc.z + b.z, 0.f);
    acc.w = fmaxf(acc.w + b.w, 0.f);
    split_store(g_hhi, g_hlo, n * 64 + t, acc);
}

// ------- gather layer 2: uvagg -> z -> za/zb (fused) -------
__global__ __launch_bounds__(32) void k_gather2(const float* __restrict__ gn,
                                                const float* __restrict__ bmu,
                                                const float* __restrict__ bsig) {
    __shared__ float srow[128];
    int n = blockIdx.x;
    int t = threadIdx.x;             // 32 threads, each a float4 of the 128-wide row
    float dv = g_dinv[n];
    float d2 = dv * dv;
    float4 acc = *((const float4*)(g_uv + (size_t)n * 128) + t);
    acc.x *= d2; acc.y *= d2; acc.z *= d2; acc.w *= d2;
    int e0 = g_off[n], e1 = g_off[n + 1];
    for (int e = e0; e < e1; e++) {
        int src = g_csr_src[e];
        float wgt = g_csr_w[e];
        float4 u = *((const float4*)(g_uv + (size_t)src * 128) + t);
        acc.x += u.x * wgt; acc.y += u.y * wgt; acc.z += u.z * wgt; acc.w += u.w * wgt;
    }
    *(float4*)(srow + 4 * t) = acc;
    __syncwarp();
    // each thread computes z for features l = 2t, 2t+1
    int l = 2 * t;
    float u0 = srow[l]     + bmu[l];
    float u1 = srow[l + 1] + bmu[l + 1];
    float s0 = srow[64 + l]     + bsig[l];
    float s1 = srow[64 + l + 1] + bsig[l + 1];
    float z0 = gn[(size_t)n * LL + l]     * expf(u0) + s0;
    float z1 = gn[(size_t)n * LL + l + 1] * expf(u1) + s1;
    bf16 h0 = __float2bfloat16_rn(z0);
    bf16 h1 = __float2bfloat16_rn(z1);
    bf16 l0 = __float2bfloat16_rn(z0 - __bfloat162float(h0));
    bf16 l1 = __float2bfloat16_rn(z1 - __bfloat162float(h1));
    __nv_bfloat162 hh(h0, h1), ll(l0, l1);
    size_t r = (size_t)n * 192;
    *(__nv_bfloat162*)(g_za + r + l)       = hh;
    *(__nv_bfloat162*)(g_za + r + 64 + l)  = hh;
    *(__nv_bfloat162*)(g_za + r + 128 + l) = ll;
    *(__nv_bfloat162*)(g_zb + r + l)       = hh;
    *(__nv_bfloat162*)(g_zb + r + 64 + l)  = ll;
    *(__nv_bfloat162*)(g_zb + r + 128 + l) = hh;
}

// ---------------- out = sigmoid(z @ z^T) via bf16 mma.sync ----------------
#define PITCH_W 100   // smem row pitch in 32-bit words (400 B)

__global__ __launch_bounds__(256, 2) void k_zzt_tc(float* __restrict__ out) {
    extern __shared__ uint32_t smw[];
    uint32_t* sB = smw + 128 * PITCH_W;
    int tid = threadIdx.x;
    int m0 = blockIdx.y * 128, n0 = blockIdx.x * 128;

    for (int i = tid; i < 128 * 24; i += 256) {
        int r = i / 24, f4 = i % 24;
        uint4 v = *((const uint4*)(g_za + (size_t)(m0 + r) * 192) + f4);
        *(uint4*)(smw + r * PITCH_W + f4 * 4) = v;
    }
    for (int i = tid; i < 128 * 24; i += 256) {
        int r = i / 24, f4 = i % 24;
        uint4 v = *((const uint4*)(g_zb + (size_t)(n0 + r) * 192) + f4);
        *(uint4*)(sB + r * PITCH_W + f4 * 4) = v;
    }
    __syncthreads();

    int w = tid >> 5, lane = tid & 31;
    int wm = (w & 3) * 32;
    int wn = (w >> 2) * 64;
    int lr = lane & 15, lc = lane >> 4;
    uint32_t baseA = (uint32_t)__cvta_generic_to_shared(smw);
    uint32_t baseB = (uint32_t)__cvta_generic_to_shared(sB);

    float acc[2][8][4];
#pragma unroll
    for (int a = 0; a < 2; a++)
#pragma unroll
        for (int b = 0; b < 8; b++)
#pragma unroll
            for (int c = 0; c < 4; c++) acc[a][b][c] = 0.f;

    for (int ks = 0; ks < 12; ks++) {
        uint32_t a0[2], a1[2], a2[2], a3[2];
#pragma unroll
        for (int mi = 0; mi < 2; mi++) {
            uint32_t ad = baseA + (uint32_t)(wm + mi * 16 + lr) * 400 + ks * 32 + lc * 16;
            ldmx4(a0[mi], a1[mi], a2[mi], a3[mi], ad);
        }
#pragma unroll
        for (int ni = 0; ni < 4; ni++) {
            uint32_t b0, b1, b2, b3;
            uint32_t bd = baseB + (uint32_t)(wn + ni * 16 + lr) * 400 + ks * 32 + lc * 16;
            ldmx4(b0, b1, b2, b3, bd);
#pragma unroll
            for (int mi = 0; mi < 2; mi++) {
                mma16816(acc[mi][ni * 2 + 0], a0[mi], a1[mi], a2[mi], a3[mi], b0, b2);
                mma16816(acc[mi][ni * 2 + 1], a0[mi], a1[mi], a2[mi], a3[mi], b1, b3);
            }
        }
    }

    int tr = lane >> 2, tc = (lane & 3) * 2;
#pragma unroll
    for (int mi = 0; mi < 2; mi++) {
#pragma unroll
        for (int nj = 0; nj < 8; nj++) {
            int gr = m0 + wm + mi * 16 + tr;
            int gc = n0 + wn + nj * 8 + tc;
            float2 v0, v1;
            v0.x = sigf(acc[mi][nj][0]); v0.y = sigf(acc[mi][nj][1]);
            v1.x = sigf(acc[mi][nj][2]); v1.y = sigf(acc[mi][nj][3]);
            *(float2*)(out + (size_t)gr * Nn + gc)       = v0;
            *(float2*)(out + (size_t)(gr + 8) * Nn + gc) = v1;
        }
    }
}

// ---------------- launch ----------------
extern "C" void kernel_launch(void* const* d_in, const int* in_sizes, int n_in,
                              void* d_out, int out_size) {
    const float* x    = (const float*)d_in[0];
    const int*   ei   = (const int*)d_in[1];
    const float* W1   = (const float*)d_in[2];
    const float* b1   = (const float*)d_in[3];
    const float* Wmu  = (const float*)d_in[4];
    const float* bmu  = (const float*)d_in[5];
    const float* Wsig = (const float*)d_in[6];
    const float* bsig = (const float*)d_in[7];
    const float* gn   = (const float*)d_in[8];
    float* out = (float*)d_out;
    (void)in_sizes; (void)n_in; (void)out_size;

    int smem_g1 = (128 + 128) * TPW * 4;   // 69632
    int smem_g2 = (64 + 128) * TPW * 4;    // 52224
    cudaFuncSetAttribute(k_gemm_tc<0>, cudaFuncAttributeMaxDynamicSharedMemorySize, smem_g1);
    cudaFuncSetAttribute(k_gemm_tc<1>, cudaFuncAttributeMaxDynamicSharedMemorySize, smem_g2);
    cudaFuncSetAttribute(k_zzt_tc, cudaFuncAttributeMaxDynamicSharedMemorySize,
                         2 * 128 * PITCH_W * 4);

    // CSR build
    k_zero_cnt<<<Nn / 256, 256>>>();
    k_deg_i<<<EE / 256, 256>>>(ei);
    k_scan<<<1, 256>>>();
    k_fill<<<EE / 256, 256>>>(ei);

    // splits for layer 1
    k_split_x<<<(Nn * FIN / 4 + 255) / 256, 256>>>(x);
    k_split_w1t<<<(FIN * HH + 255) / 256, 256>>>(W1);

    // layer 1: GEMM then CSR gather (fused bias+relu+split)
    k_gemm_tc<0><<<dim3(2, 64), 256, smem_g1>>>();
    k_gather1<<<Nn, 64>>>(b1);

    // layer 2
    k_split_wht<<<(HH * 128 + 255) / 256, 256>>>(Wmu, Wsig);
    k_gemm_tc<1><<<dim3(1, 128), 256, smem_g2>>>();
    k_gather2<<<Nn, 32>>>(gn, bmu, bsig);

    k_zzt_tc<<<dim3(Nn / 128, Nn / 128), 256, 2 * 128 * PITCH_W * 4>>>(out);
}

// round 9
// speedup vs baseline: 2.1123x; 1.2191x over previous
#include <cuda_runtime.h>
#include <cuda_bf16.h>
#include <cstdint>

// Problem constants
#define Nn  8192
#define FIN 512
#define HH  256
#define LL  64
#define EE  262144

typedef __nv_bfloat16 bf16;

// Scratch (device globals; no allocation allowed)
__device__ int   g_cnt[Nn];
__device__ int   g_off[Nn + 1];
__device__ int   g_cur[Nn];
__device__ int   g_csr_src[EE];
__device__ float g_csr_w[EE];
__device__ float g_dinv[Nn];
__device__ float g_xw1[Nn * HH];     // x @ W1 (fp32)
__device__ float g_uv[Nn * 128];     // [h@Wmu | h@Wsig]
__device__ bf16  g_za[Nn * 192];     // [hi | hi | lo]
__device__ bf16  g_zb[Nn * 192];     // [hi | lo | hi]
// bf16 split operands
__device__ bf16 g_xhi[Nn * FIN];
__device__ bf16 g_xlo[Nn * FIN];
__device__ bf16 g_w1thi[HH * FIN];   // W1^T [256][512]
__device__ bf16 g_w1tlo[HH * FIN];
__device__ bf16 g_hhi[Nn * HH];
__device__ bf16 g_hlo[Nn * HH];
__device__ bf16 g_whthi[128 * HH];   // [Wmu|Wsig]^T [128][256]
__device__ bf16 g_whtlo[128 * HH];

__device__ __forceinline__ float sigf(float x) {
    return 1.0f / (1.0f + __expf(-x));
}

// ---------------- CSR build ----------------
__global__ void k_zero_cnt() {
    int i = blockIdx.x * blockDim.x + threadIdx.x;
    if (i < Nn) g_cnt[i] = 0;
}
__global__ void k_deg_i(const int* __restrict__ ei) {
    int e = blockIdx.x * blockDim.x + threadIdx.x;
    if (e < EE) atomicAdd(&g_cnt[ei[EE + e]], 1);
}
__global__ void k_scan() {
    __shared__ int ssum[256];
    int t = threadIdx.x;
    int base = t * 32;
    int s = 0;
#pragma unroll
    for (int i = 0; i < 32; i++) s += g_cnt[base + i];
    ssum[t] = s;
    __syncthreads();
    if (t == 0) {
        int run = 0;
        for (int i = 0; i < 256; i++) { int v = ssum[i]; ssum[i] = run; run += v; }
        g_off[Nn] = run;
    }
    __syncthreads();
    int run = ssum[t];
#pragma unroll
    for (int i = 0; i < 32; i++) {
        int c = g_cnt[base + i];
        g_off[base + i] = run;
        g_cur[base + i] = run;
        g_dinv[base + i] = rsqrtf((float)c + 1.0f);
        run += c;
    }
}
__global__ void k_fill(const int* __restrict__ ei) {
    int e = blockIdx.x * blockDim.x + threadIdx.x;
    if (e < EE) {
        int src = ei[e], dst = ei[EE + e];
        int pos = atomicAdd(&g_cur[dst], 1);
        g_csr_src[pos] = src;
        g_csr_w[pos] = g_dinv[src] * g_dinv[dst];
    }
}

// ---------------- bf16 hi/lo splits ----------------
__device__ __forceinline__ void split_store(bf16* hi, bf16* lo, int i4, float4 v) {
    bf16 h0 = __float2bfloat16_rn(v.x), h1 = __float2bfloat16_rn(v.y);
    bf16 h2 = __float2bfloat16_rn(v.z), h3 = __float2bfloat16_rn(v.w);
    bf16 l0 = __float2bfloat16_rn(v.x - __bfloat162float(h0));
    bf16 l1 = __float2bfloat16_rn(v.y - __bfloat162float(h1));
    bf16 l2 = __float2bfloat16_rn(v.z - __bfloat162float(h2));
    bf16 l3 = __float2bfloat16_rn(v.w - __bfloat162float(h3));
    __nv_bfloat162* hp = (__nv_bfloat162*)(hi + (size_t)i4 * 4);
    __nv_bfloat162* lp = (__nv_bfloat162*)(lo + (size_t)i4 * 4);
    hp[0] = __nv_bfloat162(h0, h1);
    hp[1] = __nv_bfloat162(h2, h3);
    lp[0] = __nv_bfloat162(l0, l1);
    lp[1] = __nv_bfloat162(l2, l3);
}

__global__ void k_split_x(const float* __restrict__ x) {
    int i = blockIdx.x * blockDim.x + threadIdx.x;
    if (i < Nn * FIN / 4) split_store(g_xhi, g_xlo, i, *((const float4*)x + i));
}

__global__ void k_split_w1t(const float* __restrict__ W) {
    int t = blockIdx.x * blockDim.x + threadIdx.x;
    if (t < FIN * HH) {
        int k = t / HH, n = t % HH;
        float v = W[t];
        bf16 h = __float2bfloat16_rn(v);
        bf16 l = __float2bfloat16_rn(v - __bfloat162float(h));
        g_w1thi[(size_t)n * FIN + k] = h;
        g_w1tlo[(size_t)n * FIN + k] = l;
    }
}

__global__ void k_split_wht(const float* __restrict__ Wmu,
                            const float* __restrict__ Wsig) {
    int t = blockIdx.x * blockDim.x + threadIdx.x;
    if (t < HH * 128) {
        int k = t / 128, n = t % 128;
        float v = (n < 64) ? Wmu[(size_t)k * 64 + n] : Wsig[(size_t)k * 64 + (n - 64)];
        bf16 h = __float2bfloat16_rn(v);
        bf16 l = __float2bfloat16_rn(v - __bfloat162float(h));
        g_whthi[(size_t)n * HH + k] = h;
        g_whtlo[(size_t)n * HH + k] = l;
    }
}

// ---------------- mma.sync tensor-core GEMM for layers 1/2 ------
#define KT   128                  // k-tile (bf16 elems)
#define TPW  68                   // smem pitch words (272 B)

__device__ __forceinline__ void mma16816(float* d, uint32_t a0, uint32_t a1,
                                         uint32_t a2, uint32_t a3,
                                         uint32_t b0, uint32_t b1) {
    asm volatile(
        "mma.sync.aligned.m16n8k16.row.col.f32.bf16.bf16.f32 "
        "{%0,%1,%2,%3}, {%4,%5,%6,%7}, {%8,%9}, {%0,%1,%2,%3};"
        : "+f"(d[0]), "+f"(d[1]), "+f"(d[2]), "+f"(d[3])
        : "r"(a0), "r"(a1), "r"(a2), "r"(a3), "r"(b0), "r"(b1));
}
__device__ __forceinline__ void ldmx4(uint32_t& r0, uint32_t& r1, uint32_t& r2,
                                      uint32_t& r3, uint32_t addr) {
    asm volatile("ldmatrix.sync.aligned.m8n8.x4.shared.b16 {%0,%1,%2,%3}, [%4];"
                 : "=r"(r0), "=r"(r1), "=r"(r2), "=r"(r3) : "r"(addr));
}

// MODE 0: A=g_x(512), B=g_w1t -> g_xw1 (w=256), 128-row tiles
// MODE 1: A=g_h(256), B=g_wht -> g_uv  (w=128), 64-row tiles
template <int MODE>
__global__ __launch_bounds__(256) void k_gemm_tc() {
    constexpr int MI = (MODE == 0) ? 2 : 1;
    constexpr int K  = (MODE == 0) ? FIN : HH;
    constexpr int MT = 64 * MI;
    const bf16* Ahi = (MODE == 0) ? g_xhi : g_hhi;
    const bf16* Alo = (MODE == 0) ? g_xlo : g_hlo;
    const bf16* Bhi = (MODE == 0) ? g_w1thi : g_whthi;
    const bf16* Blo = (MODE == 0) ? g_w1tlo : g_whtlo;

    extern __shared__ uint32_t smw[];
    uint32_t* sB = smw + MT * TPW;
    int tid = threadIdx.x;
    int m0 = blockIdx.y * MT, n0 = blockIdx.x * 128;

    int w = tid >> 5, lane = tid & 31;
    int wm = (w & 3) * 16 * MI;
    int wn = (w >> 2) * 64;
    int lr = lane & 15, lc = lane >> 4;
    uint32_t baseA = (uint32_t)__cvta_generic_to_shared(smw);
    uint32_t baseB = (uint32_t)__cvta_generic_to_shared(sB);

    float acc[MI][8][4];
#pragma unroll
    for (int a = 0; a < MI; a++)
#pragma unroll
        for (int b = 0; b < 8; b++)
#pragma unroll
            for (int c = 0; c < 4; c++) acc[a][b][c] = 0.f;

    const bf16* pa[3] = {Ahi, Ahi, Alo};
    const bf16* pb[3] = {Bhi, Blo, Bhi};

    for (int ph = 0; ph < 3; ph++) {
        const bf16* A = pa[ph];
        const bf16* B = pb[ph];
        for (int kt = 0; kt < K; kt += KT) {
            for (int i = tid; i < MT * 16; i += 256) {
                int r = i >> 4, q = i & 15;
                uint4 v = *(const uint4*)(A + (size_t)(m0 + r) * K + kt + q * 8);
                *(uint4*)(smw + r * TPW + q * 4) = v;
            }
            for (int i = tid; i < 128 * 16; i += 256) {
                int r = i >> 4, q = i & 15;
                uint4 v = *(const uint4*)(B + (size_t)(n0 + r) * K + kt + q * 8);
                *(uint4*)(sB + r * TPW + q * 4) = v;
            }
            __syncthreads();
#pragma unroll
            for (int ks = 0; ks < KT / 16; ks++) {
                uint32_t a0[MI], a1[MI], a2[MI], a3[MI];
#pragma unroll
                for (int mi = 0; mi < MI; mi++) {
                    uint32_t ad = baseA + (uint32_t)(wm + mi * 16 + lr) * (TPW * 4)
                                + ks * 32 + lc * 16;
                    ldmx4(a0[mi], a1[mi], a2[mi], a3[mi], ad);
                }
#pragma unroll
                for (int ni = 0; ni < 4; ni++) {
                    uint32_t b0, b1, b2, b3;
                    uint32_t bd = baseB + (uint32_t)(wn + ni * 16 + lr) * (TPW * 4)
                                + ks * 32 + lc * 16;
                    ldmx4(b0, b1, b2, b3, bd);
#pragma unroll
                    for (int mi = 0; mi < MI; mi++) {
                        mma16816(acc[mi][ni * 2 + 0], a0[mi], a1[mi], a2[mi], a3[mi], b0, b2);
                        mma16816(acc[mi][ni * 2 + 1], a0[mi], a1[mi], a2[mi], a3[mi], b1, b3);
                    }
                }
            }
            __syncthreads();
        }
    }

    int tr = lane >> 2, tc = (lane & 3) * 2;
    constexpr int wout = (MODE == 0) ? 256 : 128;
    float* out1 = (MODE == 0) ? g_xw1 : g_uv;
#pragma unroll
    for (int mi = 0; mi < MI; mi++) {
#pragma unroll
        for (int half = 0; half < 2; half++) {
            int gr = m0 + wm + mi * 16 + tr + half * 8;
#pragma unroll
            for (int nj = 0; nj < 8; nj++) {
                int gc = n0 + wn + nj * 8 + tc;
                float2 o = {acc[mi][nj][half * 2 + 0], acc[mi][nj][half * 2 + 1]};
                *(float2*)(out1 + (size_t)gr * wout + gc) = o;
            }
        }
    }
}

// ------- gather layer 1: h = relu(sum_e w*xw1[src] + d2*xw1[n] + b1), split -------
__global__ __launch_bounds__(64) void k_gather1(const float* __restrict__ b1) {
    int n = blockIdx.x;
    int t = threadIdx.x;             // 64 threads, each a float4 of the 256-wide row
    float dv = g_dinv[n];
    float d2 = dv * dv;
    float4 acc = *((const float4*)(g_xw1 + (size_t)n * HH) + t);
    acc.x *= d2; acc.y *= d2; acc.z *= d2; acc.w *= d2;
    int e0 = g_off[n], e1 = g_off[n + 1];
    for (int e = e0; e < e1; e++) {
        int src = g_csr_src[e];
        float wgt = g_csr_w[e];
        float4 u = *((const float4*)(g_xw1 + (size_t)src * HH) + t);
        acc.x += u.x * wgt; acc.y += u.y * wgt; acc.z += u.z * wgt; acc.w += u.w * wgt;
    }
    float4 b = ((const float4*)b1)[t];
    acc.x = fmaxf(acc.x + b.x, 0.f);
    acc.y = fmaxf(acc.y + b.y, 0.f);
    acc.z = fmaxf(acc.z + b.z, 0.f);
    acc.w = fmaxf(acc.w + b.w, 0.f);
    split_store(g_hhi, g_hlo, n * 64 + t, acc);
}

// ------- gather layer 2: uvagg -> z -> za/zb (fused) -------
__global__ __launch_bounds__(32) void k_gather2(const float* __restrict__ gn,
                                                const float* __restrict__ bmu,
                                                const float* __restrict__ bsig) {
    __shared__ float srow[128];
    int n = blockIdx.x;
    int t = threadIdx.x;             // 32 threads, each a float4 of the 128-wide row
    float dv = g_dinv[n];
    float d2 = dv * dv;
    float4 acc = *((const float4*)(g_uv + (size_t)n * 128) + t);
    acc.x *= d2; acc.y *= d2; acc.z *= d2; acc.w *= d2;
    int e0 = g_off[n], e1 = g_off[n + 1];
    for (int e = e0; e < e1; e++) {
        int src = g_csr_src[e];
        float wgt = g_csr_w[e];
        float4 u = *((const float4*)(g_uv + (size_t)src * 128) + t);
        acc.x += u.x * wgt; acc.y += u.y * wgt; acc.z += u.z * wgt; acc.w += u.w * wgt;
    }
    *(float4*)(srow + 4 * t) = acc;
    __syncwarp();
    int l = 2 * t;
    float u0 = srow[l]     + bmu[l];
    float u1 = srow[l + 1] + bmu[l + 1];
    float s0 = srow[64 + l]     + bsig[l];
    float s1 = srow[64 + l + 1] + bsig[l + 1];
    float z0 = gn[(size_t)n * LL + l]     * expf(u0) + s0;
    float z1 = gn[(size_t)n * LL + l + 1] * expf(u1) + s1;
    bf16 h0 = __float2bfloat16_rn(z0);
    bf16 h1 = __float2bfloat16_rn(z1);
    bf16 l0 = __float2bfloat16_rn(z0 - __bfloat162float(h0));
    bf16 l1 = __float2bfloat16_rn(z1 - __bfloat162float(h1));
    __nv_bfloat162 hh(h0, h1), ll(l0, l1);
    size_t r = (size_t)n * 192;
    *(__nv_bfloat162*)(g_za + r + l)       = hh;
    *(__nv_bfloat162*)(g_za + r + 64 + l)  = hh;
    *(__nv_bfloat162*)(g_za + r + 128 + l) = ll;
    *(__nv_bfloat162*)(g_zb + r + l)       = hh;
    *(__nv_bfloat162*)(g_zb + r + 64 + l)  = ll;
    *(__nv_bfloat162*)(g_zb + r + 128 + l) = hh;
}

// ------- out = sigmoid(z @ z^T), symmetric: compute bx>=by, mirror store -------
#define PITCH_W 100   // smem row pitch in 32-bit words (400 B)
#define OPITCH  129   // fp32 output staging pitch (words)

__global__ __launch_bounds__(256, 2) void k_zzt_sym(float* __restrict__ out) {
    extern __shared__ uint32_t smw[];
    int bx = blockIdx.x, by = blockIdx.y;
    if (bx < by) return;
    uint32_t* sB = smw + 128 * PITCH_W;
    int tid = threadIdx.x;
    int m0 = by * 128, n0 = bx * 128;

    for (int i = tid; i < 128 * 24; i += 256) {
        int r = i / 24, f4 = i % 24;
        uint4 v = *((const uint4*)(g_za + (size_t)(m0 + r) * 192) + f4);
        *(uint4*)(smw + r * PITCH_W + f4 * 4) = v;
    }
    for (int i = tid; i < 128 * 24; i += 256) {
        int r = i / 24, f4 = i % 24;
        uint4 v = *((const uint4*)(g_zb + (size_t)(n0 + r) * 192) + f4);
        *(uint4*)(sB + r * PITCH_W + f4 * 4) = v;
    }
    __syncthreads();

    int w = tid >> 5, lane = tid & 31;
    int wm = (w & 3) * 32;
    int wn = (w >> 2) * 64;
    int lr = lane & 15, lc = lane >> 4;
    uint32_t baseA = (uint32_t)__cvta_generic_to_shared(smw);
    uint32_t baseB = (uint32_t)__cvta_generic_to_shared(sB);

    float acc[2][8][4];
#pragma unroll
    for (int a = 0; a < 2; a++)
#pragma unroll
        for (int b = 0; b < 8; b++)
#pragma unroll
            for (int c = 0; c < 4; c++) acc[a][b][c] = 0.f;

    for (int ks = 0; ks < 12; ks++) {
        uint32_t a0[2], a1[2], a2[2], a3[2];
#pragma unroll
        for (int mi = 0; mi < 2; mi++) {
            uint32_t ad = baseA + (uint32_t)(wm + mi * 16 + lr) * 400 + ks * 32 + lc * 16;
            ldmx4(a0[mi], a1[mi], a2[mi], a3[mi], ad);
        }
#pragma unroll
        for (int ni = 0; ni < 4; ni++) {
            uint32_t b0, b1, b2, b3;
            uint32_t bd = baseB + (uint32_t)(wn + ni * 16 + lr) * 400 + ks * 32 + lc * 16;
            ldmx4(b0, b1, b2, b3, bd);
#pragma unroll
            for (int mi = 0; mi < 2; mi++) {
                mma16816(acc[mi][ni * 2 + 0], a0[mi], a1[mi], a2[mi], a3[mi], b0, b2);
                mma16816(acc[mi][ni * 2 + 1], a0[mi], a1[mi], a2[mi], a3[mi], b1, b3);
            }
        }
    }

    // stage sigmoid(tile) in smem [128][OPITCH]
    __syncthreads();                       // all ldmatrix reads done before overwrite
    float* sO = (float*)smw;               // 128*129*4 = 66048 B < 102400 B
    int tr = lane >> 2, tc = (lane & 3) * 2;
#pragma unroll
    for (int mi = 0; mi < 2; mi++) {
#pragma unroll
        for (int nj = 0; nj < 8; nj++) {
            int rr0 = wm + mi * 16 + tr;
            int cc = wn + nj * 8 + tc;
            sO[rr0 * OPITCH + cc]           = sigf(acc[mi][nj][0]);
            sO[rr0 * OPITCH + cc + 1]       = sigf(acc[mi][nj][1]);
            sO[(rr0 + 8) * OPITCH + cc]     = sigf(acc[mi][nj][2]);
            sO[(rr0 + 8) * OPITCH + cc + 1] = sigf(acc[mi][nj][3]);
        }
    }
    __syncthreads();

    // direct store: rows m0+r, cols n0..
    for (int i = tid; i < 128 * 32; i += 256) {
        int r = i >> 5, c = (i & 31) * 4;
        float4 v = {sO[r * OPITCH + c], sO[r * OPITCH + c + 1],
                    sO[r * OPITCH + c + 2], sO[r * OPITCH + c + 3]};
        *(float4*)(out + (size_t)(m0 + r) * Nn + n0 + c) = v;
    }
    // mirror store: rows n0+r, cols m0..  (transposed read from sO)
    if (bx != by) {
        for (int i = tid; i < 128 * 32; i += 256) {
            int r = i >> 5, c = (i & 31) * 4;
            float4 v = {sO[(c + 0) * OPITCH + r], sO[(c + 1) * OPITCH + r],
                        sO[(c + 2) * OPITCH + r], sO[(c + 3) * OPITCH + r]};
            *(float4*)(out + (size_t)(n0 + r) * Nn + m0 + c) = v;
        }
    }
}

// ---------------- launch ----------------
extern "C" void kernel_launch(void* const* d_in, const int* in_sizes, int n_in,
                              void* d_out, int out_size) {
    const float* x    = (const float*)d_in[0];
    const int*   ei   = (const int*)d_in[1];
    const float* W1   = (const float*)d_in[2];
    const float* b1   = (const float*)d_in[3];
    const float* Wmu  = (const float*)d_in[4];
    const float* bmu  = (const float*)d_in[5];
    const float* Wsig = (const float*)d_in[6];
    const float* bsig = (const float*)d_in[7];
    const float* gn   = (const float*)d_in[8];
    float* out = (float*)d_out;
    (void)in_sizes; (void)n_in; (void)out_size;

    int smem_g1 = (128 + 128) * TPW * 4;   // 69632
    int smem_g2 = (64 + 128) * TPW * 4;    // 52224
    cudaFuncSetAttribute(k_gemm_tc<0>, cudaFuncAttributeMaxDynamicSharedMemorySize, smem_g1);
    cudaFuncSetAttribute(k_gemm_tc<1>, cudaFuncAttributeMaxDynamicSharedMemorySize, smem_g2);
    cudaFuncSetAttribute(k_zzt_sym, cudaFuncAttributeMaxDynamicSharedMemorySize,
                         2 * 128 * PITCH_W * 4);

    // CSR build
    k_zero_cnt<<<Nn / 256, 256>>>();
    k_deg_i<<<EE / 256, 256>>>(ei);
    k_scan<<<1, 256>>>();
    k_fill<<<EE / 256, 256>>>(ei);

    // splits for layer 1
    k_split_x<<<(Nn * FIN / 4 + 255) / 256, 256>>>(x);
    k_split_w1t<<<(FIN * HH + 255) / 256, 256>>>(W1);

    // layer 1: GEMM then CSR gather (fused bias+relu+split)
    k_gemm_tc<0><<<dim3(2, 64), 256, smem_g1>>>();
    k_gather1<<<Nn, 64>>>(b1);

    // layer 2
    k_split_wht<<<(HH * 128 + 255) / 256, 256>>>(Wmu, Wsig);
    k_gemm_tc<1><<<dim3(1, 128), 256, smem_g2>>>();
    k_gather2<<<Nn, 32>>>(gn, bmu, bsig);

    k_zzt_sym<<<dim3(Nn / 128, Nn / 128), 256, 2 * 128 * PITCH_W * 4>>>(out);
}

// round 10
// speedup vs baseline: 2.3977x; 1.1351x over previous
#include <cuda_runtime.h>
#include <cuda_bf16.h>
#include <cstdint>

// Problem constants
#define Nn  8192
#define FIN 512
#define HH  256
#define LL  64
#define EE  262144

typedef __nv_bfloat16 bf16;

// Scratch (device globals; no allocation allowed)
__device__ int   g_cnt[Nn];
__device__ int   g_off[Nn + 1];
__device__ int   g_cur[Nn];
__device__ int   g_csr_src[EE];
__device__ float g_csr_w[EE];
__device__ float g_dinv[Nn];
__device__ float g_xw1[Nn * HH];     // x @ W1 (fp32)
__device__ float g_uv[Nn * 128];     // [h@Wmu | h@Wsig]
__device__ bf16  g_za[Nn * 192];     // [hi | hi | lo]
__device__ bf16  g_zb[Nn * 192];     // [hi | lo | hi]
// bf16 split operands
__device__ bf16 g_xhi[Nn * FIN];
__device__ bf16 g_xlo[Nn * FIN];
__device__ bf16 g_w1thi[HH * FIN];   // W1^T [256][512]
__device__ bf16 g_w1tlo[HH * FIN];
__device__ bf16 g_hhi[Nn * HH];
__device__ bf16 g_hlo[Nn * HH];
__device__ bf16 g_whthi[128 * HH];   // [Wmu|Wsig]^T [128][256]
__device__ bf16 g_whtlo[128 * HH];

__device__ __forceinline__ float sigf(float x) {
    return 1.0f / (1.0f + __expf(-x));
}

// ---------------- CSR build ----------------
__global__ void k_zero_cnt() {
    int i = blockIdx.x * blockDim.x + threadIdx.x;
    if (i < Nn) g_cnt[i] = 0;
}
__global__ void k_deg_i(const int* __restrict__ ei) {
    int e = blockIdx.x * blockDim.x + threadIdx.x;
    if (e < EE) atomicAdd(&g_cnt[ei[EE + e]], 1);
}
__global__ void k_scan() {
    __shared__ int ssum[256];
    int t = threadIdx.x;
    int base = t * 32;
    int s = 0;
#pragma unroll
    for (int i = 0; i < 32; i++) s += g_cnt[base + i];
    ssum[t] = s;
    __syncthreads();
    if (t == 0) {
        int run = 0;
        for (int i = 0; i < 256; i++) { int v = ssum[i]; ssum[i] = run; run += v; }
        g_off[Nn] = run;
    }
    __syncthreads();
    int run = ssum[t];
#pragma unroll
    for (int i = 0; i < 32; i++) {
        int c = g_cnt[base + i];
        g_off[base + i] = run;
        g_cur[base + i] = run;
        g_dinv[base + i] = rsqrtf((float)c + 1.0f);
        run += c;
    }
}
__global__ void k_fill(const int* __restrict__ ei) {
    int e = blockIdx.x * blockDim.x + threadIdx.x;
    if (e < EE) {
        int src = ei[e], dst = ei[EE + e];
        int pos = atomicAdd(&g_cur[dst], 1);
        g_csr_src[pos] = src;
        g_csr_w[pos] = g_dinv[src] * g_dinv[dst];
    }
}

// ---------------- bf16 hi/lo splits ----------------
__device__ __forceinline__ void split_store(bf16* hi, bf16* lo, int i4, float4 v) {
    bf16 h0 = __float2bfloat16_rn(v.x), h1 = __float2bfloat16_rn(v.y);
    bf16 h2 = __float2bfloat16_rn(v.z), h3 = __float2bfloat16_rn(v.w);
    bf16 l0 = __float2bfloat16_rn(v.x - __bfloat162float(h0));
    bf16 l1 = __float2bfloat16_rn(v.y - __bfloat162float(h1));
    bf16 l2 = __float2bfloat16_rn(v.z - __bfloat162float(h2));
    bf16 l3 = __float2bfloat16_rn(v.w - __bfloat162float(h3));
    __nv_bfloat162* hp = (__nv_bfloat162*)(hi + (size_t)i4 * 4);
    __nv_bfloat162* lp = (__nv_bfloat162*)(lo + (size_t)i4 * 4);
    hp[0] = __nv_bfloat162(h0, h1);
    hp[1] = __nv_bfloat162(h2, h3);
    lp[0] = __nv_bfloat162(l0, l1);
    lp[1] = __nv_bfloat162(l2, l3);
}

__global__ void k_split_x(const float* __restrict__ x) {
    int i = blockIdx.x * blockDim.x + threadIdx.x;
    if (i < Nn * FIN / 4) split_store(g_xhi, g_xlo, i, *((const float4*)x + i));
}

__global__ void k_split_w1t(const float* __restrict__ W) {
    int t = blockIdx.x * blockDim.x + threadIdx.x;
    if (t < FIN * HH) {
        int k = t / HH, n = t % HH;
        float v = W[t];
        bf16 h = __float2bfloat16_rn(v);
        bf16 l = __float2bfloat16_rn(v - __bfloat162float(h));
        g_w1thi[(size_t)n * FIN + k] = h;
        g_w1tlo[(size_t)n * FIN + k] = l;
    }
}

__global__ void k_split_wht(const float* __restrict__ Wmu,
                            const float* __restrict__ Wsig) {
    int t = blockIdx.x * blockDim.x + threadIdx.x;
    if (t < HH * 128) {
        int k = t / 128, n = t % 128;
        float v = (n < 64) ? Wmu[(size_t)k * 64 + n] : Wsig[(size_t)k * 64 + (n - 64)];
        bf16 h = __float2bfloat16_rn(v);
        bf16 l = __float2bfloat16_rn(v - __bfloat162float(h));
        g_whthi[(size_t)n * HH + k] = h;
        g_whtlo[(size_t)n * HH + k] = l;
    }
}

// ---------------- mma helpers ----------------
__device__ __forceinline__ void mma16816(float* d, uint32_t a0, uint32_t a1,
                                         uint32_t a2, uint32_t a3,
                                         uint32_t b0, uint32_t b1) {
    asm volatile(
        "mma.sync.aligned.m16n8k16.row.col.f32.bf16.bf16.f32 "
        "{%0,%1,%2,%3}, {%4,%5,%6,%7}, {%8,%9}, {%0,%1,%2,%3};"
        : "+f"(d[0]), "+f"(d[1]), "+f"(d[2]), "+f"(d[3])
        : "r"(a0), "r"(a1), "r"(a2), "r"(a3), "r"(b0), "r"(b1));
}
__device__ __forceinline__ void ldmx4(uint32_t& r0, uint32_t& r1, uint32_t& r2,
                                      uint32_t& r3, uint32_t addr) {
    asm volatile("ldmatrix.sync.aligned.m8n8.x4.shared.b16 {%0,%1,%2,%3}, [%4];"
                 : "=r"(r0), "=r"(r1), "=r"(r2), "=r"(r3) : "r"(addr));
}
__device__ __forceinline__ void cpasync16(uint32_t dst, const void* src) {
    asm volatile("cp.async.cg.shared.global [%0], [%1], 16;"
                 :: "r"(dst), "l"(src) : "memory");
}

// ---------------- mma.sync GEMM for layers 1/2 (unchanged) ------
#define KT   128
#define TPW  68

template <int MODE>
__global__ __launch_bounds__(256) void k_gemm_tc() {
    constexpr int MI = (MODE == 0) ? 2 : 1;
    constexpr int K  = (MODE == 0) ? FIN : HH;
    constexpr int MT = 64 * MI;
    const bf16* Ahi = (MODE == 0) ? g_xhi : g_hhi;
    const bf16* Alo = (MODE == 0) ? g_xlo : g_hlo;
    const bf16* Bhi = (MODE == 0) ? g_w1thi : g_whthi;
    const bf16* Blo = (MODE == 0) ? g_w1tlo : g_whtlo;

    extern __shared__ uint32_t smw[];
    uint32_t* sB = smw + MT * TPW;
    int tid = threadIdx.x;
    int m0 = blockIdx.y * MT, n0 = blockIdx.x * 128;

    int w = tid >> 5, lane = tid & 31;
    int wm = (w & 3) * 16 * MI;
    int wn = (w >> 2) * 64;
    int lr = lane & 15, lc = lane >> 4;
    uint32_t baseA = (uint32_t)__cvta_generic_to_shared(smw);
    uint32_t baseB = (uint32_t)__cvta_generic_to_shared(sB);

    float acc[MI][8][4];
#pragma unroll
    for (int a = 0; a < MI; a++)
#pragma unroll
        for (int b = 0; b < 8; b++)
#pragma unroll
            for (int c = 0; c < 4; c++) acc[a][b][c] = 0.f;

    const bf16* pa[3] = {Ahi, Ahi, Alo};
    const bf16* pb[3] = {Bhi, Blo, Bhi};

    for (int ph = 0; ph < 3; ph++) {
        const bf16* A = pa[ph];
        const bf16* B = pb[ph];
        for (int kt = 0; kt < K; kt += KT) {
            for (int i = tid; i < MT * 16; i += 256) {
                int r = i >> 4, q = i & 15;
                uint4 v = *(const uint4*)(A + (size_t)(m0 + r) * K + kt + q * 8);
                *(uint4*)(smw + r * TPW + q * 4) = v;
            }
            for (int i = tid; i < 128 * 16; i += 256) {
                int r = i >> 4, q = i & 15;
                uint4 v = *(const uint4*)(B + (size_t)(n0 + r) * K + kt + q * 8);
                *(uint4*)(sB + r * TPW + q * 4) = v;
            }
            __syncthreads();
#pragma unroll
            for (int ks = 0; ks < KT / 16; ks++) {
                uint32_t a0[MI], a1[MI], a2[MI], a3[MI];
#pragma unroll
                for (int mi = 0; mi < MI; mi++) {
                    uint32_t ad = baseA + (uint32_t)(wm + mi * 16 + lr) * (TPW * 4)
                                + ks * 32 + lc * 16;
                    ldmx4(a0[mi], a1[mi], a2[mi], a3[mi], ad);
                }
#pragma unroll
                for (int ni = 0; ni < 4; ni++) {
                    uint32_t b0, b1, b2, b3;
                    uint32_t bd = baseB + (uint32_t)(wn + ni * 16 + lr) * (TPW * 4)
                                + ks * 32 + lc * 16;
                    ldmx4(b0, b1, b2, b3, bd);
#pragma unroll
                    for (int mi = 0; mi < MI; mi++) {
                        mma16816(acc[mi][ni * 2 + 0], a0[mi], a1[mi], a2[mi], a3[mi], b0, b2);
                        mma16816(acc[mi][ni * 2 + 1], a0[mi], a1[mi], a2[mi], a3[mi], b1, b3);
                    }
                }
            }
            __syncthreads();
        }
    }

    int tr = lane >> 2, tc = (lane & 3) * 2;
    constexpr int wout = (MODE == 0) ? 256 : 128;
    float* out1 = (MODE == 0) ? g_xw1 : g_uv;
#pragma unroll
    for (int mi = 0; mi < MI; mi++) {
#pragma unroll
        for (int half = 0; half < 2; half++) {
            int gr = m0 + wm + mi * 16 + tr + half * 8;
#pragma unroll
            for (int nj = 0; nj < 8; nj++) {
                int gc = n0 + wn + nj * 8 + tc;
                float2 o = {acc[mi][nj][half * 2 + 0], acc[mi][nj][half * 2 + 1]};
                *(float2*)(out1 + (size_t)gr * wout + gc) = o;
            }
        }
    }
}

// ------- gather layer 1 -------
__global__ __launch_bounds__(64) void k_gather1(const float* __restrict__ b1) {
    int n = blockIdx.x;
    int t = threadIdx.x;
    float dv = g_dinv[n];
    float d2 = dv * dv;
    float4 acc = *((const float4*)(g_xw1 + (size_t)n * HH) + t);
    acc.x *= d2; acc.y *= d2; acc.z *= d2; acc.w *= d2;
    int e0 = g_off[n], e1 = g_off[n + 1];
    for (int e = e0; e < e1; e++) {
        int src = g_csr_src[e];
        float wgt = g_csr_w[e];
        float4 u = *((const float4*)(g_xw1 + (size_t)src * HH) + t);
        acc.x += u.x * wgt; acc.y += u.y * wgt; acc.z += u.z * wgt; acc.w += u.w * wgt;
    }
    float4 b = ((const float4*)b1)[t];
    acc.x = fmaxf(acc.x + b.x, 0.f);
    acc.y = fmaxf(acc.y + b.y, 0.f);
    acc.z = fmaxf(acc.z + b.z, 0.f);
    acc.w = fmaxf(acc.w + b.w, 0.f);
    split_store(g_hhi, g_hlo, n * 64 + t, acc);
}

// ------- gather layer 2 -------
__global__ __launch_bounds__(32) void k_gather2(const float* __restrict__ gn,
                                                const float* __restrict__ bmu,
                                                const float* __restrict__ bsig) {
    __shared__ float srow[128];
    int n = blockIdx.x;
    int t = threadIdx.x;
    float dv = g_dinv[n];
    float d2 = dv * dv;
    float4 acc = *((const float4*)(g_uv + (size_t)n * 128) + t);
    acc.x *= d2; acc.y *= d2; acc.z *= d2; acc.w *= d2;
    int e0 = g_off[n], e1 = g_off[n + 1];
    for (int e = e0; e < e1; e++) {
        int src = g_csr_src[e];
        float wgt = g_csr_w[e];
        float4 u = *((const float4*)(g_uv + (size_t)src * 128) + t);
        acc.x += u.x * wgt; acc.y += u.y * wgt; acc.z += u.z * wgt; acc.w += u.w * wgt;
    }
    *(float4*)(srow + 4 * t) = acc;
    __syncwarp();
    int l = 2 * t;
    float u0 = srow[l]     + bmu[l];
    float u1 = srow[l + 1] + bmu[l + 1];
    float s0 = srow[64 + l]     + bsig[l];
    float s1 = srow[64 + l + 1] + bsig[l + 1];
    float z0 = gn[(size_t)n * LL + l]     * expf(u0) + s0;
    float z1 = gn[(size_t)n * LL + l + 1] * expf(u1) + s1;
    bf16 h0 = __float2bfloat16_rn(z0);
    bf16 h1 = __float2bfloat16_rn(z1);
    bf16 l0 = __float2bfloat16_rn(z0 - __bfloat162float(h0));
    bf16 l1 = __float2bfloat16_rn(z1 - __bfloat162float(h1));
    __nv_bfloat162 hh(h0, h1), ll(l0, l1);
    size_t r = (size_t)n * 192;
    *(__nv_bfloat162*)(g_za + r + l)       = hh;
    *(__nv_bfloat162*)(g_za + r + 64 + l)  = hh;
    *(__nv_bfloat162*)(g_za + r + 128 + l) = ll;
    *(__nv_bfloat162*)(g_zb + r + l)       = hh;
    *(__nv_bfloat162*)(g_zb + r + 64 + l)  = ll;
    *(__nv_bfloat162*)(g_zb + r + 128 + l) = hh;
}

// ------- out = sigmoid(z z^T): triangular grid + cp.async 2-stage pipeline ---
#define ZPW     52                  // stage smem pitch words (208 B; 208/16=13 odd)
#define STG_W   (128 * ZPW)         // words per tile buffer (A or B)
#define STAGE_W (2 * STG_W)         // words per pipeline stage (A+B)
#define OPITCH  129                 // fp32 output staging pitch (words)
#define NTRI    2080                // 64*65/2 lower-triangle tiles

__global__ __launch_bounds__(256, 2) void k_zzt_sym(float* __restrict__ out) {
    extern __shared__ uint32_t smw[];
    int t5 = blockIdx.x;
    // decode lower-triangle (by, bx) with bx >= by; cum(r) = 64r - r(r-1)/2
    int by = (int)(64.5f - sqrtf(64.5f * 64.5f - 2.0f * (float)t5));
    while (64 * (by + 1) - ((by + 1) * by) / 2 <= t5) by++;
    while (64 * by - (by * (by - 1)) / 2 > t5) by--;
    int bx = by + (t5 - (64 * by - (by * (by - 1)) / 2));
    int m0 = by * 128, n0 = bx * 128;

    int tid = threadIdx.x;
    uint32_t sbase = (uint32_t)__cvta_generic_to_shared(smw);

    // issue both pipeline stages (K halves of 96 cols)
#pragma unroll
    for (int st = 0; st < 2; st++) {
        uint32_t dA = sbase + st * (STAGE_W * 4);
        uint32_t dB = dA + STG_W * 4;
        for (int i = tid; i < 128 * 12; i += 256) {
            int r = i / 12, q = i % 12;
            cpasync16(dA + r * 208 + q * 16,
                      g_za + (size_t)(m0 + r) * 192 + st * 96 + q * 8);
            cpasync16(dB + r * 208 + q * 16,
                      g_zb + (size_t)(n0 + r) * 192 + st * 96 + q * 8);
        }
        asm volatile("cp.async.commit_group;" ::: "memory");
    }

    int w = tid >> 5, lane = tid & 31;
    int wm = (w & 3) * 32;
    int wn = (w >> 2) * 64;
    int lr = lane & 15, lc = lane >> 4;

    float acc[2][8][4];
#pragma unroll
    for (int a = 0; a < 2; a++)
#pragma unroll
        for (int b = 0; b < 8; b++)
#pragma unroll
            for (int c = 0; c < 4; c++) acc[a][b][c] = 0.f;

#pragma unroll
    for (int st = 0; st < 2; st++) {
        if (st == 0) {
            asm volatile("cp.async.wait_group 1;" ::: "memory");
        } else {
            asm volatile("cp.async.wait_group 0;" ::: "memory");
        }
        __syncthreads();
        uint32_t baseA = sbase + st * (STAGE_W * 4);
        uint32_t baseB = baseA + STG_W * 4;
#pragma unroll
        for (int ks = 0; ks < 6; ks++) {
            uint32_t a0[2], a1[2], a2[2], a3[2];
#pragma unroll
            for (int mi = 0; mi < 2; mi++) {
                uint32_t ad = baseA + (uint32_t)(wm + mi * 16 + lr) * 208 + ks * 32 + lc * 16;
                ldmx4(a0[mi], a1[mi], a2[mi], a3[mi], ad);
            }
#pragma unroll
            for (int ni = 0; ni < 4; ni++) {
                uint32_t b0, b1, b2, b3;
                uint32_t bd = baseB + (uint32_t)(wn + ni * 16 + lr) * 208 + ks * 32 + lc * 16;
                ldmx4(b0, b1, b2, b3, bd);
#pragma unroll
                for (int mi = 0; mi < 2; mi++) {
                    mma16816(acc[mi][ni * 2 + 0], a0[mi], a1[mi], a2[mi], a3[mi], b0, b2);
                    mma16816(acc[mi][ni * 2 + 1], a0[mi], a1[mi], a2[mi], a3[mi], b1, b3);
                }
            }
        }
    }

    // stage sigmoid(tile) in smem [128][OPITCH]
    __syncthreads();
    float* sO = (float*)smw;      // 66048 B < pipeline area, compute done
    int tr = lane >> 2, tc = (lane & 3) * 2;
#pragma unroll
    for (int mi = 0; mi < 2; mi++) {
#pragma unroll
        for (int nj = 0; nj < 8; nj++) {
            int rr0 = wm + mi * 16 + tr;
            int cc = wn + nj * 8 + tc;
            sO[rr0 * OPITCH + cc]           = sigf(acc[mi][nj][0]);
            sO[rr0 * OPITCH + cc + 1]       = sigf(acc[mi][nj][1]);
            sO[(rr0 + 8) * OPITCH + cc]     = sigf(acc[mi][nj][2]);
            sO[(rr0 + 8) * OPITCH + cc + 1] = sigf(acc[mi][nj][3]);
        }
    }
    __syncthreads();

    // direct store
    for (int i = tid; i < 128 * 32; i += 256) {
        int r = i >> 5, c = (i & 31) * 4;
        float4 v = {sO[r * OPITCH + c], sO[r * OPITCH + c + 1],
                    sO[r * OPITCH + c + 2], sO[r * OPITCH + c + 3]};
        *(float4*)(out + (size_t)(m0 + r) * Nn + n0 + c) = v;
    }
    // mirror store (transposed)
    if (bx != by) {
        for (int i = tid; i < 128 * 32; i += 256) {
            int r = i >> 5, c = (i & 31) * 4;
            float4 v = {sO[(c + 0) * OPITCH + r], sO[(c + 1) * OPITCH + r],
                        sO[(c + 2) * OPITCH + r], sO[(c + 3) * OPITCH + r]};
            *(float4*)(out + (size_t)(n0 + r) * Nn + m0 + c) = v;
        }
    }
}

// ---------------- launch ----------------
extern "C" void kernel_launch(void* const* d_in, const int* in_sizes, int n_in,
                              void* d_out, int out_size) {
    const float* x    = (const float*)d_in[0];
    const int*   ei   = (const int*)d_in[1];
    const float* W1   = (const float*)d_in[2];
    const float* b1   = (const float*)d_in[3];
    const float* Wmu  = (const float*)d_in[4];
    const float* bmu  = (const float*)d_in[5];
    const float* Wsig = (const float*)d_in[6];
    const float* bsig = (const float*)d_in[7];
    const float* gn   = (const float*)d_in[8];
    float* out = (float*)d_out;
    (void)in_sizes; (void)n_in; (void)out_size;

    int smem_g1 = (128 + 128) * TPW * 4;
    int smem_g2 = (64 + 128) * TPW * 4;
    int smem_zz = 2 * STAGE_W * 4;          // 106496 B
    cudaFuncSetAttribute(k_gemm_tc<0>, cudaFuncAttributeMaxDynamicSharedMemorySize, smem_g1);
    cudaFuncSetAttribute(k_gemm_tc<1>, cudaFuncAttributeMaxDynamicSharedMemorySize, smem_g2);
    cudaFuncSetAttribute(k_zzt_sym, cudaFuncAttributeMaxDynamicSharedMemorySize, smem_zz);

    // CSR build
    k_zero_cnt<<<Nn / 256, 256>>>();
    k_deg_i<<<EE / 256, 256>>>(ei);
    k_scan<<<1, 256>>>();
    k_fill<<<EE / 256, 256>>>(ei);

    // splits for layer 1
    k_split_x<<<(Nn * FIN / 4 + 255) / 256, 256>>>(x);
    k_split_w1t<<<(FIN * HH + 255) / 256, 256>>>(W1);

    // layer 1
    k_gemm_tc<0><<<dim3(2, 64), 256, smem_g1>>>();
    k_gather1<<<Nn, 64>>>(b1);

    // layer 2
    k_split_wht<<<(HH * 128 + 255) / 256, 256>>>(Wmu, Wsig);
    k_gemm_tc<1><<<dim3(1, 128), 256, smem_g2>>>();
    k_gather2<<<Nn, 32>>>(gn, bmu, bsig);

    k_zzt_sym<<<NTRI, 256, smem_zz>>>(out);
}